// round 13
// baseline (speedup 1.0000x reference)
#include <cuda_runtime.h>
#include <cuda_fp16.h>
#include <math.h>
#include <stdint.h>

// Problem constants
#define NB   64      // batch
#define NM   512     // memory slots
#define NE   256     // embedding dim
#define NT   32      // decode steps
#define NV   32000   // vocab
#define NTR  4       // tokens per memory slot
#define NG   768     // 3*NE gate dim
#define KX   512     // 2*NE vocab-GEMM K

// Output layout: [T,B,V] vocab | [T,B,M] ptr | [1,B,E] h
#define OUT_PTR  ((size_t)NT*NB*NV)
#define OUT_H    (OUT_PTR + (size_t)NT*NB*NM)

// ---------------- scratch ----------------
__device__ float g_mem[6ull*NB*NM*NE];   // 201 MB
__device__ float g_q  [NB*NE];
__device__ float g_H  [(size_t)NT*NB*NE];
__device__ float g_xin[(size_t)NT*NB*NE];
__device__ float g_gi [(size_t)NT*NB*NG];
__device__ float g_qc [(size_t)NT*NB*NE];
__device__ float g_O  [(size_t)NT*NB*NE];
__device__ float g_Sdump[(size_t)NT*NB*NM];
__device__ __half g_Wth[(size_t)NE*NG];  // W_hh transposed fp16: g_Wth[k*NG+j]
__device__ __half g_Wh[(size_t)NV*KX];
__device__ __half g_Xh[(size_t)NT*NB*KX];

// ---------------- 1) embedding sums (float4, validated R12 @74us) --------------
__global__ void k_embed(const int* __restrict__ inp,
                        const float* __restrict__ encC,
                        const float* __restrict__ decC) {
    size_t idx = (size_t)blockIdx.x * 256 + threadIdx.x;  // over 6*NB*NM*64
    int e4  = (int)(idx & 63);
    size_t r = idx >> 6;
    int bm  = (int)(r % (NB * NM));
    int tbl = (int)(r / (NB * NM));
    int b = bm / NM, m = bm % NM;
    const float* tab = (tbl < 3) ? (encC + (size_t)(tbl + 1) * NV * NE)
                                 : (decC + (size_t)(tbl - 3) * NV * NE);
    const float4* tab4 = (const float4*)tab;
    const int* ix = inp + ((size_t)m * NB + b) * NTR;
    float4 s = {0.f, 0.f, 0.f, 0.f};
    for (int tr = 0; tr < NTR; tr++) {
        float4 v = tab4[(size_t)ix[tr] * 64 + e4];
        s.x += v.x; s.y += v.y; s.z += v.z; s.w += v.w;
    }
    ((float4*)g_mem)[((size_t)tbl * NB * NM + bm) * 64 + e4] = s;
}

// ---------------- W_hh transpose -> fp16 (tiled, coalesced) --------------------
__global__ void k_whh_t(const float* __restrict__ W) {
    __shared__ float t[32][33];
    int j0 = blockIdx.x * 32, k0 = blockIdx.y * 32;
    t[threadIdx.y][threadIdx.x] = W[(size_t)(j0 + threadIdx.y) * NE + k0 + threadIdx.x];
    __syncthreads();
    g_Wth[(size_t)(k0 + threadIdx.y) * NG + j0 + threadIdx.x] =
        __float2half_rn(t[threadIdx.x][threadIdx.y]);
}

// ---------------- 2) encoder hop0 mean ----------------
__global__ void k_mean() {
    int b = blockIdx.x, e = threadIdx.x;
    const float* memb = g_mem + ((size_t)b * NM) * NE;
    float acc = 0.f;
    for (int m = 0; m < NM; m++) acc += memb[(size_t)m * NE + e];
    g_q[b * NE + e] = acc * (1.0f / NM);
}

// ---------------- encoder fused hop v2 (validated, 37us) -----------------------
__global__ void k_hop_enc(const float* __restrict__ Q, int tblS, int tblA,
                          float* __restrict__ O) {
    __shared__ float q[NE];
    __shared__ float sc[NM];
    __shared__ float red[40];
    __shared__ float part[4][NE];
    int b = blockIdx.x;
    int tid = threadIdx.x, w = tid >> 5, lane = tid & 31;   // 1024 threads
    if (tid < NE) q[tid] = Q[(size_t)b * NE + tid];
    __syncthreads();
    const float* MS = g_mem + ((size_t)tblS * NB * NM + (size_t)b * NM) * NE;
    for (int j = 0; j < 16; j++) {
        int m = w * 16 + j;
        const float* rowp = MS + (size_t)m * NE;
        float a = 0.f;
#pragma unroll
        for (int i = 0; i < 8; i++) a += rowp[i * 32 + lane] * q[i * 32 + lane];
#pragma unroll
        for (int off = 16; off; off >>= 1) a += __shfl_xor_sync(0xffffffffu, a, off);
        if (lane == 0) sc[m] = a;
    }
    __syncthreads();
    float v = 0.f, e = 0.f;
    if (tid < 512) {
        v = sc[tid];
        float mx = v;
#pragma unroll
        for (int off = 16; off; off >>= 1) mx = fmaxf(mx, __shfl_xor_sync(0xffffffffu, mx, off));
        if (lane == 0) red[w] = mx;
    }
    __syncthreads();
    if (tid == 0) {
        float m8 = red[0];
        for (int i = 1; i < 16; i++) m8 = fmaxf(m8, red[i]);
        red[32] = m8;
    }
    __syncthreads();
    if (tid < 512) {
        e = expf(v - red[32]);
        float s = e;
#pragma unroll
        for (int off = 16; off; off >>= 1) s += __shfl_xor_sync(0xffffffffu, s, off);
        if (lane == 0) red[16 + w] = s;
    }
    __syncthreads();
    if (tid == 0) {
        float t = 0.f;
        for (int i = 0; i < 16; i++) t += red[16 + i];
        red[33] = t;
    }
    __syncthreads();
    if (tid < 512) sc[tid] = e * (1.0f / red[33]);
    __syncthreads();
    const float* MA = g_mem + ((size_t)tblA * NB * NM + (size_t)b * NM) * NE;
    int qd = tid >> 8, ee = tid & 255;
    float acc = 0.f;
#pragma unroll 4
    for (int m = qd * 128; m < qd * 128 + 128; m++)
        acc += sc[m] * MA[(size_t)m * NE + ee];
    part[qd][ee] = acc;
    __syncthreads();
    if (tid < NE)
        O[(size_t)b * NE + tid] = q[tid] + part[0][tid] + part[1][tid]
                                         + part[2][tid] + part[3][tid];
}

// ---------------- batched decoder hop (validated; used for hop 0 only) ---------
__global__ void k_hop_dec(const float* __restrict__ Q, int tblS, int tblA,
                          float* __restrict__ O) {
    __shared__ float q[8][NE];
    __shared__ float sc[8][NM];
    int b = blockIdx.x, tg = blockIdx.y;
    int tid = threadIdx.x, w = tid >> 5, lane = tid & 31;
#pragma unroll
    for (int i = 0; i < 8; i++)
        q[i][tid] = Q[((size_t)(tg * 8 + i) * NB + b) * NE + tid];
    __syncthreads();
    const float* MS = g_mem + ((size_t)tblS * NB * NM + (size_t)b * NM) * NE;
    for (int j = 0; j < 64; j++) {
        int m = w * 64 + j;
        const float* rowp = MS + (size_t)m * NE;
        float mv[8];
#pragma unroll
        for (int i = 0; i < 8; i++) mv[i] = rowp[i * 32 + lane];
#pragma unroll
        for (int t = 0; t < 8; t++) {
            float a = 0.f;
#pragma unroll
            for (int i = 0; i < 8; i++) a += mv[i] * q[t][i * 32 + lane];
#pragma unroll
            for (int off = 16; off; off >>= 1) a += __shfl_xor_sync(0xffffffffu, a, off);
            if (lane == 0) sc[t][m] = a;
        }
    }
    __syncthreads();
    {
        int t = w;
        float mx = -INFINITY;
#pragma unroll
        for (int i = 0; i < 16; i++) mx = fmaxf(mx, sc[t][i * 32 + lane]);
#pragma unroll
        for (int off = 16; off; off >>= 1) mx = fmaxf(mx, __shfl_xor_sync(0xffffffffu, mx, off));
        float ev[16], sum = 0.f;
#pragma unroll
        for (int i = 0; i < 16; i++) { ev[i] = expf(sc[t][i * 32 + lane] - mx); sum += ev[i]; }
#pragma unroll
        for (int off = 16; off; off >>= 1) sum += __shfl_xor_sync(0xffffffffu, sum, off);
        float inv = 1.0f / sum;
#pragma unroll
        for (int i = 0; i < 16; i++) sc[t][i * 32 + lane] = ev[i] * inv;
    }
    __syncthreads();
    const float* MA = g_mem + ((size_t)tblA * NB * NM + (size_t)b * NM) * NE;
    float acc[8] = {};
#pragma unroll 4
    for (int m = 0; m < NM; m++) {
        float mval = MA[(size_t)m * NE + tid];
#pragma unroll
        for (int t = 0; t < 8; t++) acc[t] += sc[t][m] * mval;
    }
#pragma unroll
    for (int t = 0; t < 8; t++)
        O[((size_t)(tg * 8 + t) * NB + b) * NE + tid] = acc[t];
}

// ---------------- decoder input embeddings ----------------
__global__ void k_xin(const int* __restrict__ tgt, const float* __restrict__ decC) {
    int tb = blockIdx.x;
    int t = tb / NB, b = tb % NB;
    int y = (t == 0) ? 2 : tgt[(t - 1) * NB + b];
    g_xin[(size_t)tb * NE + threadIdx.x] = decC[(size_t)y * NE + threadIdx.x];
}

// ---------------- register-tiled SGEMM (validated) for gi ----------------
__global__ __launch_bounds__(256, 2)
void k_sgemm(const float* __restrict__ A, const float* __restrict__ B,
             const float* __restrict__ bias, float* __restrict__ C,
             int M, int N, int K) {
    __shared__ float As[8][132];
    __shared__ float Bs[8][132];
    int tid = threadIdx.x;
    int m0 = blockIdx.y * 128, n0 = blockIdx.x * 128;
    int lr = tid >> 1;
    int lk = (tid & 1) * 4;
    const float* Ag = A + (size_t)(m0 + lr) * K + lk;
    const float* Bg = B + (size_t)(n0 + lr) * K + lk;
    int ty = tid >> 4, tx = tid & 15;
    float acc[8][8] = {};
    for (int k0 = 0; k0 < K; k0 += 8) {
        float4 av = *(const float4*)(Ag + k0);
        float4 bv = *(const float4*)(Bg + k0);
        As[lk + 0][lr] = av.x; As[lk + 1][lr] = av.y;
        As[lk + 2][lr] = av.z; As[lk + 3][lr] = av.w;
        Bs[lk + 0][lr] = bv.x; Bs[lk + 1][lr] = bv.y;
        Bs[lk + 2][lr] = bv.z; Bs[lk + 3][lr] = bv.w;
        __syncthreads();
#pragma unroll
        for (int kk = 0; kk < 8; kk++) {
            float a[8], b[8];
            *(float4*)&a[0] = *(const float4*)&As[kk][ty * 4];
            *(float4*)&a[4] = *(const float4*)&As[kk][64 + ty * 4];
            *(float4*)&b[0] = *(const float4*)&Bs[kk][tx * 4];
            *(float4*)&b[4] = *(const float4*)&Bs[kk][64 + tx * 4];
#pragma unroll
            for (int i = 0; i < 8; i++)
#pragma unroll
                for (int j = 0; j < 8; j++) acc[i][j] += a[i] * b[j];
        }
        __syncthreads();
    }
    float bb[8];
#pragma unroll
    for (int j = 0; j < 4; j++) {
        bb[j]     = bias[n0 + tx * 4 + j];
        bb[4 + j] = bias[n0 + 64 + tx * 4 + j];
    }
#pragma unroll
    for (int i = 0; i < 8; i++) {
        int m = m0 + ((i < 4) ? (ty * 4 + i) : (64 + ty * 4 + i - 4));
        float4 c0, c1;
        c0.x = acc[i][0] + bb[0]; c0.y = acc[i][1] + bb[1];
        c0.z = acc[i][2] + bb[2]; c0.w = acc[i][3] + bb[3];
        c1.x = acc[i][4] + bb[4]; c1.y = acc[i][5] + bb[5];
        c1.z = acc[i][6] + bb[6]; c1.w = acc[i][7] + bb[7];
        *(float4*)(C + (size_t)m * N + n0 + tx * 4) = c0;
        *(float4*)(C + (size_t)m * N + n0 + 64 + tx * 4) = c1;
    }
}

// ---------------- GRU v3: coalesced fp16 transposed-W reads --------------------
__global__ void k_gru(const float* __restrict__ bhh, float* __restrict__ out_h) {
    __shared__ float h[NE];
    __shared__ float gh[NG];
    int b = blockIdx.x, tid = threadIdx.x;   // 768 threads, one gate row each
    if (tid < NE) h[tid] = g_q[b * NE + tid];
    float bias = bhh[tid];
    __syncthreads();
    for (int t = 0; t < NT; t++) {
        float acc = bias;
#pragma unroll 8
        for (int k = 0; k < NE; k++)
            acc += __half2float(g_Wth[(size_t)k * NG + tid]) * h[k];
        gh[tid] = acc;
        __syncthreads();
        if (tid < NE) {
            const float* gi = g_gi + ((size_t)t * NB + b) * NG;
            float r = 1.0f / (1.0f + expf(-(gi[tid] + gh[tid])));
            float z = 1.0f / (1.0f + expf(-(gi[NE + tid] + gh[NE + tid])));
            float n = tanhf(gi[2 * NE + tid] + r * gh[2 * NE + tid]);
            float hn = (1.0f - z) * n + z * h[tid];
            h[tid] = hn;
            g_H[((size_t)t * NB + b) * NE + tid] = hn;
            if (t == NT - 1) out_h[b * NE + tid] = hn;
        }
        __syncthreads();
    }
}

// ---------------- W_vocab -> fp16 ----------------
__global__ void k_cvt_w(const float* __restrict__ W) {
    size_t i = (size_t)blockIdx.x * 256 + threadIdx.x;
    g_Wh[i] = __float2half_rn(W[i]);
}

// ---------------- hop-0 fuse: qc = H+O0, X=[H|O0] -> fp16 ----------------
__global__ void k_fuse0() {
    int i = blockIdx.x * 256 + threadIdx.x;
    int e = i & (NE - 1);
    int tb = i >> 8;
    float hq = g_H[i], o = g_O[i];
    g_qc[i] = hq + o;
    size_t xi = (size_t)tb * KX + e;
    g_Xh[xi]      = __float2half_rn(hq);
    g_Xh[xi + NE] = __float2half_rn(o);
}

// ================ combined vocab GEMM + hop1/hop2 tail blocks ==================
#define MMAH16816(d, a, b) \
  asm volatile("mma.sync.aligned.m16n8k16.row.col.f32.f16.f16.f32 " \
    "{%0,%1,%2,%3}, {%4,%5,%6,%7}, {%8,%9}, {%0,%1,%2,%3};" \
    : "+f"(d[0]), "+f"(d[1]), "+f"(d[2]), "+f"(d[3]) \
    : "r"(a[0]), "r"(a[1]), "r"(a[2]), "r"(a[3]), "r"(b[0]), "r"(b[1]))

__device__ __forceinline__ void cp16(uint32_t dst, const void* src) {
    asm volatile("cp.async.cg.shared.global [%0], [%1], 16;\n" :: "r"(dst), "l"(src));
}

// hop1 (softmax attn over tbl4-scores, apply tbl5) + qc update + hop2 raw scores.
// One block per (b, tg): 8 queries. smem = q[8][NE] (8KB) + sc[8][NM] (16KB).
__device__ void hop12_body(void* smraw, int bx, float* __restrict__ Sout) {
    float (*q)[NE]  = (float(*)[NE])smraw;
    float (*sc)[NM] = (float(*)[NM])((char*)smraw + 8 * NE * sizeof(float));
    int b = bx & (NB - 1), tg = bx >> 6;
    int tid = threadIdx.x, w = tid >> 5, lane = tid & 31;
#pragma unroll
    for (int i = 0; i < 8; i++)
        q[i][tid] = g_qc[((size_t)(tg * 8 + i) * NB + b) * NE + tid];
    __syncthreads();
    const float* MS = g_mem + ((size_t)4 * NB * NM + (size_t)b * NM) * NE;
    const float* MA = g_mem + ((size_t)5 * NB * NM + (size_t)b * NM) * NE;
    // hop1 scores vs table 4
    for (int j = 0; j < 64; j++) {
        int m = w * 64 + j;
        const float* rowp = MS + (size_t)m * NE;
        float mv[8];
#pragma unroll
        for (int i = 0; i < 8; i++) mv[i] = rowp[i * 32 + lane];
#pragma unroll
        for (int t = 0; t < 8; t++) {
            float a = 0.f;
#pragma unroll
            for (int i = 0; i < 8; i++) a += mv[i] * q[t][i * 32 + lane];
#pragma unroll
            for (int off = 16; off; off >>= 1) a += __shfl_xor_sync(0xffffffffu, a, off);
            if (lane == 0) sc[t][m] = a;
        }
    }
    __syncthreads();
    // softmax: warp w owns row t=w
    {
        int t = w;
        float mx = -INFINITY;
#pragma unroll
        for (int i = 0; i < 16; i++) mx = fmaxf(mx, sc[t][i * 32 + lane]);
#pragma unroll
        for (int off = 16; off; off >>= 1) mx = fmaxf(mx, __shfl_xor_sync(0xffffffffu, mx, off));
        float ev[16], sum = 0.f;
#pragma unroll
        for (int i = 0; i < 16; i++) { ev[i] = expf(sc[t][i * 32 + lane] - mx); sum += ev[i]; }
#pragma unroll
        for (int off = 16; off; off >>= 1) sum += __shfl_xor_sync(0xffffffffu, sum, off);
        float inv = 1.0f / sum;
#pragma unroll
        for (int i = 0; i < 16; i++) sc[t][i * 32 + lane] = ev[i] * inv;
    }
    __syncthreads();
    // apply table 5 -> O, then qc2 = qc + O in smem
    float acc[8] = {};
#pragma unroll 4
    for (int m = 0; m < NM; m++) {
        float mval = MA[(size_t)m * NE + tid];
#pragma unroll
        for (int t = 0; t < 8; t++) acc[t] += sc[t][m] * mval;
    }
    __syncthreads();
#pragma unroll
    for (int t = 0; t < 8; t++) q[t][tid] += acc[t];
    __syncthreads();
    // hop2 raw scores vs table 5 -> sc, then coalesced write
    for (int j = 0; j < 64; j++) {
        int m = w * 64 + j;
        const float* rowp = MA + (size_t)m * NE;
        float mv[8];
#pragma unroll
        for (int i = 0; i < 8; i++) mv[i] = rowp[i * 32 + lane];
#pragma unroll
        for (int t = 0; t < 8; t++) {
            float a = 0.f;
#pragma unroll
            for (int i = 0; i < 8; i++) a += mv[i] * q[t][i * 32 + lane];
#pragma unroll
            for (int off = 16; off; off >>= 1) a += __shfl_xor_sync(0xffffffffu, a, off);
            if (lane == 0) sc[t][m] = a;
        }
    }
    __syncthreads();
#pragma unroll
    for (int t = 0; t < 8; t++) {
        size_t row = (size_t)(tg * 8 + t) * NB + b;
        Sout[row * NM + tid]       = sc[t][tid];
        Sout[row * NM + 256 + tid] = sc[t][tid + 256];
    }
}

// grid (256, 17): y<16 & x<250 -> GEMM tile; y==16 -> hop12 block (x = b + 64*tg)
__global__ __launch_bounds__(256)
void k_hgemm_hop(const float* __restrict__ bias, float* __restrict__ C,
                 float* __restrict__ Sout) {
    __shared__ __align__(16) unsigned char sm[24576];   // GEMM: 2x12288; hop12: q+sc
    if (blockIdx.y == 16) { hop12_body(sm, blockIdx.x, Sout); return; }
    if (blockIdx.x >= NV / 128) return;
    int tid = threadIdx.x;
    int n0 = blockIdx.x * 128, m0 = blockIdx.y * 128;
    int wid = tid >> 5, lane = tid & 31;
    int wm = (wid >> 2) * 64, wn = (wid & 3) * 32;
    int g = lane >> 2, tg = lane & 3;
    uint32_t sbase = (uint32_t)__cvta_generic_to_shared(sm);
    int lr = tid >> 1, lkc = tid & 1;

    const __half* srcA = g_Xh + (size_t)(m0 + lr) * KX + lkc * 8;
    const __half* srcB = g_Wh + (size_t)(n0 + lr) * KX + lkc * 8;
    uint32_t dbase = sbase + lr * 48 + lkc * 16;

    float acc[4][4][4] = {};

    cp16(dbase,        srcA);
    cp16(dbase + 6144, srcB);
    asm volatile("cp.async.commit_group;\n" ::);

    for (int it = 0; it < KX / 16; it++) {
        if (it + 1 < KX / 16) {
            uint32_t d2 = dbase + ((it + 1) & 1) * 12288;
            int koff = (it + 1) * 16;
            cp16(d2,        srcA + koff);
            cp16(d2 + 6144, srcB + koff);
            asm volatile("cp.async.commit_group;\n" ::);
            asm volatile("cp.async.wait_group 1;\n" ::);
        } else {
            asm volatile("cp.async.wait_group 0;\n" ::);
        }
        __syncthreads();
        const char* sb = (const char*)sm + (it & 1) * 12288;
        const __half* Ah = (const __half*)(sb);
        const __half* Bh = (const __half*)(sb + 6144);
        uint32_t ah[4][4];
        int c = tg * 2;
#pragma unroll
        for (int f = 0; f < 4; f++) {
            int r = wm + f * 16 + g;
            ah[f][0] = *(const uint32_t*)&Ah[r * 24 + c];
            ah[f][1] = *(const uint32_t*)&Ah[(r + 8) * 24 + c];
            ah[f][2] = *(const uint32_t*)&Ah[r * 24 + c + 8];
            ah[f][3] = *(const uint32_t*)&Ah[(r + 8) * 24 + c + 8];
        }
#pragma unroll
        for (int fn = 0; fn < 4; fn++) {
            int r = wn + fn * 8 + g;
            uint32_t bh[2];
            bh[0] = *(const uint32_t*)&Bh[r * 24 + c];
            bh[1] = *(const uint32_t*)&Bh[r * 24 + c + 8];
#pragma unroll
            for (int f = 0; f < 4; f++)
                MMAH16816(acc[f][fn], ah[f], bh);
        }
        __syncthreads();
    }
#pragma unroll
    for (int f = 0; f < 4; f++) {
        int rbase = m0 + wm + f * 16 + g;
#pragma unroll
        for (int fn = 0; fn < 4; fn++) {
            int c0 = n0 + wn + fn * 8 + tg * 2;
            float b0v = bias[c0], b1v = bias[c0 + 1];
            float2 v0 = {acc[f][fn][0] + b0v, acc[f][fn][1] + b1v};
            float2 v1 = {acc[f][fn][2] + b0v, acc[f][fn][3] + b1v};
            *(float2*)(C + (size_t)rbase * NV + c0) = v0;
            *(float2*)(C + (size_t)(rbase + 8) * NV + c0) = v1;
        }
    }
}

// ---------------- launch ----------------
extern "C" void kernel_launch(void* const* d_in, const int* in_sizes, int n_in,
                              void* d_out, int out_size) {
    const int*   inp    = (const int*)d_in[0];
    const int*   tgt    = (const int*)d_in[1];
    const float* encC   = (const float*)d_in[2];
    const float* decC   = (const float*)d_in[3];
    const float* W_ih   = (const float*)d_in[4];
    const float* W_hh   = (const float*)d_in[5];
    const float* b_ih   = (const float*)d_in[6];
    const float* b_hh   = (const float*)d_in[7];
    const float* W_voc  = (const float*)d_in[8];
    const float* b_voc  = (const float*)d_in[9];
    float* out = (float*)d_out;

    float *gq, *gO, *gH, *gxin, *ggi;
    cudaGetSymbolAddress((void**)&gq,   g_q);
    cudaGetSymbolAddress((void**)&gO,   g_O);
    cudaGetSymbolAddress((void**)&gH,   g_H);
    cudaGetSymbolAddress((void**)&gxin, g_xin);
    cudaGetSymbolAddress((void**)&ggi,  g_gi);

    // dependency-free setup first
    k_cvt_w<<<(unsigned)(((size_t)NV * KX) / 256), 256>>>(W_voc);
    k_whh_t<<<dim3(NG / 32, NE / 32), dim3(32, 32)>>>(W_hh);
    k_xin<<<NT * NB, NE>>>(tgt, decC);
    k_embed<<<(unsigned)((6ull * NB * NM * 64) / 256), 256>>>(inp, encC, decC);

    // ---- encoder: hop0 mean, then 2 fused hops ----
    k_mean<<<NB, 256>>>();
    k_hop_enc<<<NB, 1024>>>(gq, 0, 1, gq);
    k_hop_enc<<<NB, 1024>>>(gq, 1, 2, gq);

    // ---- decoder setup + GRU (fp16 transposed W) ----
    k_sgemm<<<dim3(NG / 128, (NT * NB) / 128), 256>>>(gxin, W_ih, b_ih, ggi, NT * NB, NG, NE);
    k_gru<<<NB, NG>>>(b_hh, out + OUT_H);

    // ---- decoder hop 0 (batched) -> O0; build qc and fp16 X ----
    k_hop_dec<<<dim3(NB, NT / 8), 256>>>(gH, 3, 4, gO);
    k_fuse0<<<(NT * NB * NE) / 256, 256>>>();

    // ---- vocab GEMM + hop1/hop2 tail blocks in ONE launch ----
    k_hgemm_hop<<<dim3(256, 17), 256>>>(b_voc, out, out + OUT_PTR);
}

// round 14
// speedup vs baseline: 1.0027x; 1.0027x over previous
#include <cuda_runtime.h>
#include <cuda_fp16.h>
#include <math.h>
#include <stdint.h>

// Problem constants
#define NB   64      // batch
#define NM   512     // memory slots
#define NE   256     // embedding dim
#define NT   32      // decode steps
#define NV   32000   // vocab
#define NTR  4       // tokens per memory slot
#define NG   768     // 3*NE gate dim
#define KX   512     // 2*NE vocab-GEMM K

// Output layout: [T,B,V] vocab | [T,B,M] ptr | [1,B,E] h
#define OUT_PTR  ((size_t)NT*NB*NV)
#define OUT_H    (OUT_PTR + (size_t)NT*NB*NM)

// ---------------- scratch ----------------
__device__ float g_mem[6ull*NB*NM*NE];   // 201 MB
__device__ float g_q  [NB*NE];
__device__ float g_H  [(size_t)NT*NB*NE];
__device__ float g_xin[(size_t)NT*NB*NE];
__device__ float g_gi [(size_t)NT*NB*NG];
__device__ float g_qc [(size_t)NT*NB*NE];
__device__ float g_O  [(size_t)NT*NB*NE];
__device__ float g_Sdump[(size_t)NT*NB*NM];
__device__ float g_probe[(size_t)NT*NB*NV];   // probe GEMM dead output (262 MB)
__device__ __half g_Wth[(size_t)NE*NG];  // W_hh transposed fp16
__device__ __half g_Wh[(size_t)NV*KX];
__device__ __half g_Xh[(size_t)NT*NB*KX];

// ---------------- 1) embedding sums (float4, validated @74us) ------------------
__global__ void k_embed(const int* __restrict__ inp,
                        const float* __restrict__ encC,
                        const float* __restrict__ decC) {
    size_t idx = (size_t)blockIdx.x * 256 + threadIdx.x;  // over 6*NB*NM*64
    int e4  = (int)(idx & 63);
    size_t r = idx >> 6;
    int bm  = (int)(r % (NB * NM));
    int tbl = (int)(r / (NB * NM));
    int b = bm / NM, m = bm % NM;
    const float* tab = (tbl < 3) ? (encC + (size_t)(tbl + 1) * NV * NE)
                                 : (decC + (size_t)(tbl - 3) * NV * NE);
    const float4* tab4 = (const float4*)tab;
    const int* ix = inp + ((size_t)m * NB + b) * NTR;
    float4 s = {0.f, 0.f, 0.f, 0.f};
    for (int tr = 0; tr < NTR; tr++) {
        float4 v = tab4[(size_t)ix[tr] * 64 + e4];
        s.x += v.x; s.y += v.y; s.z += v.z; s.w += v.w;
    }
    ((float4*)g_mem)[((size_t)tbl * NB * NM + bm) * 64 + e4] = s;
}

// ---------------- W_hh transpose -> fp16 (tiled, coalesced) --------------------
__global__ void k_whh_t(const float* __restrict__ W) {
    __shared__ float t[32][33];
    int j0 = blockIdx.x * 32, k0 = blockIdx.y * 32;
    t[threadIdx.y][threadIdx.x] = W[(size_t)(j0 + threadIdx.y) * NE + k0 + threadIdx.x];
    __syncthreads();
    g_Wth[(size_t)(k0 + threadIdx.y) * NG + j0 + threadIdx.x] =
        __float2half_rn(t[threadIdx.x][threadIdx.y]);
}

// ---------------- 2) encoder hop0 mean ----------------
__global__ void k_mean() {
    int b = blockIdx.x, e = threadIdx.x;
    const float* memb = g_mem + ((size_t)b * NM) * NE;
    float acc = 0.f;
    for (int m = 0; m < NM; m++) acc += memb[(size_t)m * NE + e];
    g_q[b * NE + e] = acc * (1.0f / NM);
}

// ---------------- encoder fused hop v2 (validated, 37us) -----------------------
__global__ void k_hop_enc(const float* __restrict__ Q, int tblS, int tblA,
                          float* __restrict__ O) {
    __shared__ float q[NE];
    __shared__ float sc[NM];
    __shared__ float red[40];
    __shared__ float part[4][NE];
    int b = blockIdx.x;
    int tid = threadIdx.x, w = tid >> 5, lane = tid & 31;   // 1024 threads
    if (tid < NE) q[tid] = Q[(size_t)b * NE + tid];
    __syncthreads();
    const float* MS = g_mem + ((size_t)tblS * NB * NM + (size_t)b * NM) * NE;
    for (int j = 0; j < 16; j++) {
        int m = w * 16 + j;
        const float* rowp = MS + (size_t)m * NE;
        float a = 0.f;
#pragma unroll
        for (int i = 0; i < 8; i++) a += rowp[i * 32 + lane] * q[i * 32 + lane];
#pragma unroll
        for (int off = 16; off; off >>= 1) a += __shfl_xor_sync(0xffffffffu, a, off);
        if (lane == 0) sc[m] = a;
    }
    __syncthreads();
    float v = 0.f, e = 0.f;
    if (tid < 512) {
        v = sc[tid];
        float mx = v;
#pragma unroll
        for (int off = 16; off; off >>= 1) mx = fmaxf(mx, __shfl_xor_sync(0xffffffffu, mx, off));
        if (lane == 0) red[w] = mx;
    }
    __syncthreads();
    if (tid == 0) {
        float m8 = red[0];
        for (int i = 1; i < 16; i++) m8 = fmaxf(m8, red[i]);
        red[32] = m8;
    }
    __syncthreads();
    if (tid < 512) {
        e = expf(v - red[32]);
        float s = e;
#pragma unroll
        for (int off = 16; off; off >>= 1) s += __shfl_xor_sync(0xffffffffu, s, off);
        if (lane == 0) red[16 + w] = s;
    }
    __syncthreads();
    if (tid == 0) {
        float t = 0.f;
        for (int i = 0; i < 16; i++) t += red[16 + i];
        red[33] = t;
    }
    __syncthreads();
    if (tid < 512) sc[tid] = e * (1.0f / red[33]);
    __syncthreads();
    const float* MA = g_mem + ((size_t)tblA * NB * NM + (size_t)b * NM) * NE;
    int qd = tid >> 8, ee = tid & 255;
    float acc = 0.f;
#pragma unroll 4
    for (int m = qd * 128; m < qd * 128 + 128; m++)
        acc += sc[m] * MA[(size_t)m * NE + ee];
    part[qd][ee] = acc;
    __syncthreads();
    if (tid < NE)
        O[(size_t)b * NE + tid] = q[tid] + part[0][tid] + part[1][tid]
                                         + part[2][tid] + part[3][tid];
}

// ---------------- batched decoder hop (validated; hop 0 only) ------------------
__global__ void k_hop_dec(const float* __restrict__ Q, int tblS, int tblA,
                          float* __restrict__ O) {
    __shared__ float q[8][NE];
    __shared__ float sc[8][NM];
    int b = blockIdx.x, tg = blockIdx.y;
    int tid = threadIdx.x, w = tid >> 5, lane = tid & 31;
#pragma unroll
    for (int i = 0; i < 8; i++)
        q[i][tid] = Q[((size_t)(tg * 8 + i) * NB + b) * NE + tid];
    __syncthreads();
    const float* MS = g_mem + ((size_t)tblS * NB * NM + (size_t)b * NM) * NE;
    for (int j = 0; j < 64; j++) {
        int m = w * 64 + j;
        const float* rowp = MS + (size_t)m * NE;
        float mv[8];
#pragma unroll
        for (int i = 0; i < 8; i++) mv[i] = rowp[i * 32 + lane];
#pragma unroll
        for (int t = 0; t < 8; t++) {
            float a = 0.f;
#pragma unroll
            for (int i = 0; i < 8; i++) a += mv[i] * q[t][i * 32 + lane];
#pragma unroll
            for (int off = 16; off; off >>= 1) a += __shfl_xor_sync(0xffffffffu, a, off);
            if (lane == 0) sc[t][m] = a;
        }
    }
    __syncthreads();
    {
        int t = w;
        float mx = -INFINITY;
#pragma unroll
        for (int i = 0; i < 16; i++) mx = fmaxf(mx, sc[t][i * 32 + lane]);
#pragma unroll
        for (int off = 16; off; off >>= 1) mx = fmaxf(mx, __shfl_xor_sync(0xffffffffu, mx, off));
        float ev[16], sum = 0.f;
#pragma unroll
        for (int i = 0; i < 16; i++) { ev[i] = expf(sc[t][i * 32 + lane] - mx); sum += ev[i]; }
#pragma unroll
        for (int off = 16; off; off >>= 1) sum += __shfl_xor_sync(0xffffffffu, sum, off);
        float inv = 1.0f / sum;
#pragma unroll
        for (int i = 0; i < 16; i++) sc[t][i * 32 + lane] = ev[i] * inv;
    }
    __syncthreads();
    const float* MA = g_mem + ((size_t)tblA * NB * NM + (size_t)b * NM) * NE;
    float acc[8] = {};
#pragma unroll 4
    for (int m = 0; m < NM; m++) {
        float mval = MA[(size_t)m * NE + tid];
#pragma unroll
        for (int t = 0; t < 8; t++) acc[t] += sc[t][m] * mval;
    }
#pragma unroll
    for (int t = 0; t < 8; t++)
        O[((size_t)(tg * 8 + t) * NB + b) * NE + tid] = acc[t];
}

// ---------------- decoder input embeddings ----------------
__global__ void k_xin(const int* __restrict__ tgt, const float* __restrict__ decC) {
    int tb = blockIdx.x;
    int t = tb / NB, b = tb % NB;
    int y = (t == 0) ? 2 : tgt[(t - 1) * NB + b];
    g_xin[(size_t)tb * NE + threadIdx.x] = decC[(size_t)y * NE + threadIdx.x];
}

// ---------------- register-tiled SGEMM (validated) for gi ----------------
__global__ __launch_bounds__(256, 2)
void k_sgemm(const float* __restrict__ A, const float* __restrict__ B,
             const float* __restrict__ bias, float* __restrict__ C,
             int M, int N, int K) {
    __shared__ float As[8][132];
    __shared__ float Bs[8][132];
    int tid = threadIdx.x;
    int m0 = blockIdx.y * 128, n0 = blockIdx.x * 128;
    int lr = tid >> 1;
    int lk = (tid & 1) * 4;
    const float* Ag = A + (size_t)(m0 + lr) * K + lk;
    const float* Bg = B + (size_t)(n0 + lr) * K + lk;
    int ty = tid >> 4, tx = tid & 15;
    float acc[8][8] = {};
    for (int k0 = 0; k0 < K; k0 += 8) {
        float4 av = *(const float4*)(Ag + k0);
        float4 bv = *(const float4*)(Bg + k0);
        As[lk + 0][lr] = av.x; As[lk + 1][lr] = av.y;
        As[lk + 2][lr] = av.z; As[lk + 3][lr] = av.w;
        Bs[lk + 0][lr] = bv.x; Bs[lk + 1][lr] = bv.y;
        Bs[lk + 2][lr] = bv.z; Bs[lk + 3][lr] = bv.w;
        __syncthreads();
#pragma unroll
        for (int kk = 0; kk < 8; kk++) {
            float a[8], b[8];
            *(float4*)&a[0] = *(const float4*)&As[kk][ty * 4];
            *(float4*)&a[4] = *(const float4*)&As[kk][64 + ty * 4];
            *(float4*)&b[0] = *(const float4*)&Bs[kk][tx * 4];
            *(float4*)&b[4] = *(const float4*)&Bs[kk][64 + tx * 4];
#pragma unroll
            for (int i = 0; i < 8; i++)
#pragma unroll
                for (int j = 0; j < 8; j++) acc[i][j] += a[i] * b[j];
        }
        __syncthreads();
    }
    float bb[8];
#pragma unroll
    for (int j = 0; j < 4; j++) {
        bb[j]     = bias[n0 + tx * 4 + j];
        bb[4 + j] = bias[n0 + 64 + tx * 4 + j];
    }
#pragma unroll
    for (int i = 0; i < 8; i++) {
        int m = m0 + ((i < 4) ? (ty * 4 + i) : (64 + ty * 4 + i - 4));
        float4 c0, c1;
        c0.x = acc[i][0] + bb[0]; c0.y = acc[i][1] + bb[1];
        c0.z = acc[i][2] + bb[2]; c0.w = acc[i][3] + bb[3];
        c1.x = acc[i][4] + bb[4]; c1.y = acc[i][5] + bb[5];
        c1.z = acc[i][6] + bb[6]; c1.w = acc[i][7] + bb[7];
        *(float4*)(C + (size_t)m * N + n0 + tx * 4) = c0;
        *(float4*)(C + (size_t)m * N + n0 + 64 + tx * 4) = c1;
    }
}

// ---------------- GRU v3 (validated) ----------------
__global__ void k_gru(const float* __restrict__ bhh, float* __restrict__ out_h) {
    __shared__ float h[NE];
    __shared__ float gh[NG];
    int b = blockIdx.x, tid = threadIdx.x;
    if (tid < NE) h[tid] = g_q[b * NE + tid];
    float bias = bhh[tid];
    __syncthreads();
    for (int t = 0; t < NT; t++) {
        float acc = bias;
#pragma unroll 8
        for (int k = 0; k < NE; k++)
            acc += __half2float(g_Wth[(size_t)k * NG + tid]) * h[k];
        gh[tid] = acc;
        __syncthreads();
        if (tid < NE) {
            const float* gi = g_gi + ((size_t)t * NB + b) * NG;
            float r = 1.0f / (1.0f + expf(-(gi[tid] + gh[tid])));
            float z = 1.0f / (1.0f + expf(-(gi[NE + tid] + gh[NE + tid])));
            float n = tanhf(gi[2 * NE + tid] + r * gh[2 * NE + tid]);
            float hn = (1.0f - z) * n + z * h[tid];
            h[tid] = hn;
            g_H[((size_t)t * NB + b) * NE + tid] = hn;
            if (t == NT - 1) out_h[b * NE + tid] = hn;
        }
        __syncthreads();
    }
}

// ---------------- W_vocab -> fp16 (half2 vectorized) ----------------
__global__ void k_cvt_w(const float* __restrict__ W) {
    size_t i = ((size_t)blockIdx.x * 256 + threadIdx.x) * 2;
    float2 v = *(const float2*)(W + i);
    *(__half2*)(g_Wh + i) = __floats2half2_rn(v.x, v.y);
}

// ---------------- hop-0 fuse: qc = H+O0, X=[H|O0] -> fp16 ----------------
__global__ void k_fuse0() {
    int i = blockIdx.x * 256 + threadIdx.x;
    int e = i & (NE - 1);
    int tb = i >> 8;
    float hq = g_H[i], o = g_O[i];
    g_qc[i] = hq + o;
    size_t xi = (size_t)tb * KX + e;
    g_Xh[xi]      = __float2half_rn(hq);
    g_Xh[xi + NE] = __float2half_rn(o);
}

// ================ combined vocab GEMM + hop1/hop2 tail blocks ==================
#define MMAH16816(d, a, b) \
  asm volatile("mma.sync.aligned.m16n8k16.row.col.f32.f16.f16.f32 " \
    "{%0,%1,%2,%3}, {%4,%5,%6,%7}, {%8,%9}, {%0,%1,%2,%3};" \
    : "+f"(d[0]), "+f"(d[1]), "+f"(d[2]), "+f"(d[3]) \
    : "r"(a[0]), "r"(a[1]), "r"(a[2]), "r"(a[3]), "r"(b[0]), "r"(b[1]))

__device__ __forceinline__ void cp16(uint32_t dst, const void* src) {
    asm volatile("cp.async.cg.shared.global [%0], [%1], 16;\n" :: "r"(dst), "l"(src));
}

// hop1 + qc update + hop2 raw scores (validated R13)
__device__ void hop12_body(void* smraw, int bx, float* __restrict__ Sout) {
    float (*q)[NE]  = (float(*)[NE])smraw;
    float (*sc)[NM] = (float(*)[NM])((char*)smraw + 8 * NE * sizeof(float));
    int b = bx & (NB - 1), tg = bx >> 6;
    int tid = threadIdx.x, w = tid >> 5, lane = tid & 31;
#pragma unroll
    for (int i = 0; i < 8; i++)
        q[i][tid] = g_qc[((size_t)(tg * 8 + i) * NB + b) * NE + tid];
    __syncthreads();
    const float* MS = g_mem + ((size_t)4 * NB * NM + (size_t)b * NM) * NE;
    const float* MA = g_mem + ((size_t)5 * NB * NM + (size_t)b * NM) * NE;
    for (int j = 0; j < 64; j++) {
        int m = w * 64 + j;
        const float* rowp = MS + (size_t)m * NE;
        float mv[8];
#pragma unroll
        for (int i = 0; i < 8; i++) mv[i] = rowp[i * 32 + lane];
#pragma unroll
        for (int t = 0; t < 8; t++) {
            float a = 0.f;
#pragma unroll
            for (int i = 0; i < 8; i++) a += mv[i] * q[t][i * 32 + lane];
#pragma unroll
            for (int off = 16; off; off >>= 1) a += __shfl_xor_sync(0xffffffffu, a, off);
            if (lane == 0) sc[t][m] = a;
        }
    }
    __syncthreads();
    {
        int t = w;
        float mx = -INFINITY;
#pragma unroll
        for (int i = 0; i < 16; i++) mx = fmaxf(mx, sc[t][i * 32 + lane]);
#pragma unroll
        for (int off = 16; off; off >>= 1) mx = fmaxf(mx, __shfl_xor_sync(0xffffffffu, mx, off));
        float ev[16], sum = 0.f;
#pragma unroll
        for (int i = 0; i < 16; i++) { ev[i] = expf(sc[t][i * 32 + lane] - mx); sum += ev[i]; }
#pragma unroll
        for (int off = 16; off; off >>= 1) sum += __shfl_xor_sync(0xffffffffu, sum, off);
        float inv = 1.0f / sum;
#pragma unroll
        for (int i = 0; i < 16; i++) sc[t][i * 32 + lane] = ev[i] * inv;
    }
    __syncthreads();
    float acc[8] = {};
#pragma unroll 4
    for (int m = 0; m < NM; m++) {
        float mval = MA[(size_t)m * NE + tid];
#pragma unroll
        for (int t = 0; t < 8; t++) acc[t] += sc[t][m] * mval;
    }
    __syncthreads();
#pragma unroll
    for (int t = 0; t < 8; t++) q[t][tid] += acc[t];
    __syncthreads();
    for (int j = 0; j < 64; j++) {
        int m = w * 64 + j;
        const float* rowp = MA + (size_t)m * NE;
        float mv[8];
#pragma unroll
        for (int i = 0; i < 8; i++) mv[i] = rowp[i * 32 + lane];
#pragma unroll
        for (int t = 0; t < 8; t++) {
            float a = 0.f;
#pragma unroll
            for (int i = 0; i < 8; i++) a += mv[i] * q[t][i * 32 + lane];
#pragma unroll
            for (int off = 16; off; off >>= 1) a += __shfl_xor_sync(0xffffffffu, a, off);
            if (lane == 0) sc[t][m] = a;
        }
    }
    __syncthreads();
#pragma unroll
    for (int t = 0; t < 8; t++) {
        size_t row = (size_t)(tg * 8 + t) * NB + b;
        Sout[row * NM + tid]       = sc[t][tid];
        Sout[row * NM + 256 + tid] = sc[t][tid + 256];
    }
}

// grid (x, y): y<16 & x<250 -> GEMM tile; y==16 -> hop12 block (x = b + 64*tg)
__global__ __launch_bounds__(256)
void k_hgemm_hop(const float* __restrict__ bias, float* __restrict__ C,
                 float* __restrict__ Sout) {
    __shared__ __align__(16) unsigned char sm[24576];
    if (blockIdx.y == 16) { hop12_body(sm, blockIdx.x, Sout); return; }
    if (blockIdx.x >= NV / 128) return;
    int tid = threadIdx.x;
    int n0 = blockIdx.x * 128, m0 = blockIdx.y * 128;
    int wid = tid >> 5, lane = tid & 31;
    int wm = (wid >> 2) * 64, wn = (wid & 3) * 32;
    int g = lane >> 2, tg = lane & 3;
    uint32_t sbase = (uint32_t)__cvta_generic_to_shared(sm);
    int lr = tid >> 1, lkc = tid & 1;

    const __half* srcA = g_Xh + (size_t)(m0 + lr) * KX + lkc * 8;
    const __half* srcB = g_Wh + (size_t)(n0 + lr) * KX + lkc * 8;
    uint32_t dbase = sbase + lr * 48 + lkc * 16;

    float acc[4][4][4] = {};

    cp16(dbase,        srcA);
    cp16(dbase + 6144, srcB);
    asm volatile("cp.async.commit_group;\n" ::);

    for (int it = 0; it < KX / 16; it++) {
        if (it + 1 < KX / 16) {
            uint32_t d2 = dbase + ((it + 1) & 1) * 12288;
            int koff = (it + 1) * 16;
            cp16(d2,        srcA + koff);
            cp16(d2 + 6144, srcB + koff);
            asm volatile("cp.async.commit_group;\n" ::);
            asm volatile("cp.async.wait_group 1;\n" ::);
        } else {
            asm volatile("cp.async.wait_group 0;\n" ::);
        }
        __syncthreads();
        const char* sb = (const char*)sm + (it & 1) * 12288;
        const __half* Ah = (const __half*)(sb);
        const __half* Bh = (const __half*)(sb + 6144);
        uint32_t ah[4][4];
        int c = tg * 2;
#pragma unroll
        for (int f = 0; f < 4; f++) {
            int r = wm + f * 16 + g;
            ah[f][0] = *(const uint32_t*)&Ah[r * 24 + c];
            ah[f][1] = *(const uint32_t*)&Ah[(r + 8) * 24 + c];
            ah[f][2] = *(const uint32_t*)&Ah[r * 24 + c + 8];
            ah[f][3] = *(const uint32_t*)&Ah[(r + 8) * 24 + c + 8];
        }
#pragma unroll
        for (int fn = 0; fn < 4; fn++) {
            int r = wn + fn * 8 + g;
            uint32_t bh[2];
            bh[0] = *(const uint32_t*)&Bh[r * 24 + c];
            bh[1] = *(const uint32_t*)&Bh[r * 24 + c + 8];
#pragma unroll
            for (int f = 0; f < 4; f++)
                MMAH16816(acc[f][fn], ah[f], bh);
        }
        __syncthreads();
    }
#pragma unroll
    for (int f = 0; f < 4; f++) {
        int rbase = m0 + wm + f * 16 + g;
#pragma unroll
        for (int fn = 0; fn < 4; fn++) {
            int c0 = n0 + wn + fn * 8 + tg * 2;
            float b0v = bias[c0], b1v = bias[c0 + 1];
            float2 v0 = {acc[f][fn][0] + b0v, acc[f][fn][1] + b1v};
            float2 v1 = {acc[f][fn][2] + b0v, acc[f][fn][3] + b1v};
            *(float2*)(C + (size_t)rbase * NV + c0) = v0;
            *(float2*)(C + (size_t)(rbase + 8) * NV + c0) = v1;
        }
    }
}

// ---------------- launch ----------------
extern "C" void kernel_launch(void* const* d_in, const int* in_sizes, int n_in,
                              void* d_out, int out_size) {
    const int*   inp    = (const int*)d_in[0];
    const int*   tgt    = (const int*)d_in[1];
    const float* encC   = (const float*)d_in[2];
    const float* decC   = (const float*)d_in[3];
    const float* W_ih   = (const float*)d_in[4];
    const float* W_hh   = (const float*)d_in[5];
    const float* b_ih   = (const float*)d_in[6];
    const float* b_hh   = (const float*)d_in[7];
    const float* W_voc  = (const float*)d_in[8];
    const float* b_voc  = (const float*)d_in[9];
    float* out = (float*)d_out;

    float *gq, *gO, *gH, *gxin, *ggi, *gS0, *gprobe;
    cudaGetSymbolAddress((void**)&gq,    g_q);
    cudaGetSymbolAddress((void**)&gO,    g_O);
    cudaGetSymbolAddress((void**)&gH,    g_H);
    cudaGetSymbolAddress((void**)&gxin,  g_xin);
    cudaGetSymbolAddress((void**)&ggi,   g_gi);
    cudaGetSymbolAddress((void**)&gS0,   g_Sdump);
    cudaGetSymbolAddress((void**)&gprobe, g_probe);

    // dependency-free setup; launch idx 3 = GEMM PROBE (ncu captures idx 3).
    k_cvt_w<<<(unsigned)(((size_t)NV * KX) / 512), 256>>>(W_voc);            // 0
    k_whh_t<<<dim3(NG / 32, NE / 32), dim3(32, 32)>>>(W_hh);                 // 1
    k_xin<<<NT * NB, NE>>>(tgt, decC);                                       // 2
    // PROBE: 1/15.6-scale replay of the production GEMM on current g_Xh/g_Wh;
    // dead output (g_probe). Deterministic per replay; real GEMM below is final.
    k_hgemm_hop<<<dim3(16, 16), 256>>>(b_voc, gprobe, gS0);                  // 3
    k_embed<<<(unsigned)((6ull * NB * NM * 64) / 256), 256>>>(inp, encC, decC);

    // ---- encoder ----
    k_mean<<<NB, 256>>>();
    k_hop_enc<<<NB, 1024>>>(gq, 0, 1, gq);
    k_hop_enc<<<NB, 1024>>>(gq, 1, 2, gq);

    // ---- decoder setup + GRU ----
    k_sgemm<<<dim3(NG / 128, (NT * NB) / 128), 256>>>(gxin, W_ih, b_ih, ggi, NT * NB, NG, NE);
    k_gru<<<NB, NG>>>(b_hh, out + OUT_H);

    // ---- decoder hop 0 -> O0; build qc and fp16 X ----
    k_hop_dec<<<dim3(NB, NT / 8), 256>>>(gH, 3, 4, gO);
    k_fuse0<<<(NT * NB * NE) / 256, 256>>>();

    // ---- vocab GEMM + hop1/hop2 tail blocks ----
    k_hgemm_hop<<<dim3(256, 17), 256>>>(b_voc, out, out + OUT_PTR);
}

// round 15
// speedup vs baseline: 1.1764x; 1.1733x over previous
#include <cuda_runtime.h>
#include <cuda_fp16.h>
#include <math.h>
#include <stdint.h>

// Problem constants
#define NB   64      // batch
#define NM   512     // memory slots
#define NE   256     // embedding dim
#define NT   32      // decode steps
#define NV   32000   // vocab
#define NTR  4       // tokens per memory slot
#define NG   768     // 3*NE gate dim
#define KX   512     // 2*NE vocab-GEMM K

// Output layout: [T,B,V] vocab | [T,B,M] ptr | [1,B,E] h
#define OUT_PTR  ((size_t)NT*NB*NV)
#define OUT_H    (OUT_PTR + (size_t)NT*NB*NM)

// ---------------- scratch ----------------
__device__ float g_mem[6ull*NB*NM*NE];   // 201 MB
__device__ float g_q  [NB*NE];
__device__ float g_H  [(size_t)NT*NB*NE];
__device__ float g_xin[(size_t)NT*NB*NE];
__device__ float g_gi [(size_t)NT*NB*NG];
__device__ float g_qc [(size_t)NT*NB*NE];
__device__ float g_O  [(size_t)NT*NB*NE];
__device__ __half2 g_Wt2[(size_t)(NE/2)*NG];  // W_hh paired-k fp16: g_Wt2[k2*NG+j]={W[j][2k2],W[j][2k2+1]}
__device__ __half g_Wh[(size_t)NV*KX];
__device__ __half g_Xh[(size_t)NT*NB*KX];

// ---------------- 1) embedding sums (float4, validated @74us) ------------------
__global__ void k_embed(const int* __restrict__ inp,
                        const float* __restrict__ encC,
                        const float* __restrict__ decC) {
    size_t idx = (size_t)blockIdx.x * 256 + threadIdx.x;  // over 6*NB*NM*64
    int e4  = (int)(idx & 63);
    size_t r = idx >> 6;
    int bm  = (int)(r % (NB * NM));
    int tbl = (int)(r / (NB * NM));
    int b = bm / NM, m = bm % NM;
    const float* tab = (tbl < 3) ? (encC + (size_t)(tbl + 1) * NV * NE)
                                 : (decC + (size_t)(tbl - 3) * NV * NE);
    const float4* tab4 = (const float4*)tab;
    const int* ix = inp + ((size_t)m * NB + b) * NTR;
    float4 s = {0.f, 0.f, 0.f, 0.f};
    for (int tr = 0; tr < NTR; tr++) {
        float4 v = tab4[(size_t)ix[tr] * 64 + e4];
        s.x += v.x; s.y += v.y; s.z += v.z; s.w += v.w;
    }
    ((float4*)g_mem)[((size_t)tbl * NB * NM + bm) * 64 + e4] = s;
}

// ---------------- W_hh transpose -> paired half2 layout ------------------------
__global__ void k_whh_t(const float* __restrict__ W) {
    __shared__ float t[32][33];
    int j0 = blockIdx.x * 32, k0 = blockIdx.y * 32;
    // t[j_local][k_local]
    t[threadIdx.y][threadIdx.x] = W[(size_t)(j0 + threadIdx.y) * NE + k0 + threadIdx.x];
    __syncthreads();
    if (threadIdx.y < 16) {
        int kl = threadIdx.y * 2;
        __half2 v = __floats2half2_rn(t[threadIdx.x][kl], t[threadIdx.x][kl + 1]);
        g_Wt2[(size_t)((k0 + kl) >> 1) * NG + j0 + threadIdx.x] = v;
    }
}

// ---------------- 2) encoder hop0 mean ----------------
__global__ void k_mean() {
    int b = blockIdx.x, e = threadIdx.x;
    const float* memb = g_mem + ((size_t)b * NM) * NE;
    float acc = 0.f;
    for (int m = 0; m < NM; m++) acc += memb[(size_t)m * NE + e];
    g_q[b * NE + e] = acc * (1.0f / NM);
}

// ---------------- encoder fused hop v2 (validated, 37us) -----------------------
__global__ void k_hop_enc(const float* __restrict__ Q, int tblS, int tblA,
                          float* __restrict__ O) {
    __shared__ float q[NE];
    __shared__ float sc[NM];
    __shared__ float red[40];
    __shared__ float part[4][NE];
    int b = blockIdx.x;
    int tid = threadIdx.x, w = tid >> 5, lane = tid & 31;   // 1024 threads
    if (tid < NE) q[tid] = Q[(size_t)b * NE + tid];
    __syncthreads();
    const float* MS = g_mem + ((size_t)tblS * NB * NM + (size_t)b * NM) * NE;
    for (int j = 0; j < 16; j++) {
        int m = w * 16 + j;
        const float* rowp = MS + (size_t)m * NE;
        float a = 0.f;
#pragma unroll
        for (int i = 0; i < 8; i++) a += rowp[i * 32 + lane] * q[i * 32 + lane];
#pragma unroll
        for (int off = 16; off; off >>= 1) a += __shfl_xor_sync(0xffffffffu, a, off);
        if (lane == 0) sc[m] = a;
    }
    __syncthreads();
    float v = 0.f, e = 0.f;
    if (tid < 512) {
        v = sc[tid];
        float mx = v;
#pragma unroll
        for (int off = 16; off; off >>= 1) mx = fmaxf(mx, __shfl_xor_sync(0xffffffffu, mx, off));
        if (lane == 0) red[w] = mx;
    }
    __syncthreads();
    if (tid == 0) {
        float m8 = red[0];
        for (int i = 1; i < 16; i++) m8 = fmaxf(m8, red[i]);
        red[32] = m8;
    }
    __syncthreads();
    if (tid < 512) {
        e = expf(v - red[32]);
        float s = e;
#pragma unroll
        for (int off = 16; off; off >>= 1) s += __shfl_xor_sync(0xffffffffu, s, off);
        if (lane == 0) red[16 + w] = s;
    }
    __syncthreads();
    if (tid == 0) {
        float t = 0.f;
        for (int i = 0; i < 16; i++) t += red[16 + i];
        red[33] = t;
    }
    __syncthreads();
    if (tid < 512) sc[tid] = e * (1.0f / red[33]);
    __syncthreads();
    const float* MA = g_mem + ((size_t)tblA * NB * NM + (size_t)b * NM) * NE;
    int qd = tid >> 8, ee = tid & 255;
    float acc = 0.f;
#pragma unroll 4
    for (int m = qd * 128; m < qd * 128 + 128; m++)
        acc += sc[m] * MA[(size_t)m * NE + ee];
    part[qd][ee] = acc;
    __syncthreads();
    if (tid < NE)
        O[(size_t)b * NE + tid] = q[tid] + part[0][tid] + part[1][tid]
                                         + part[2][tid] + part[3][tid];
}

// ---------------- batched decoder hop (validated; hop 0 only) ------------------
__global__ void k_hop_dec(const float* __restrict__ Q, int tblS, int tblA,
                          float* __restrict__ O) {
    __shared__ float q[8][NE];
    __shared__ float sc[8][NM];
    int b = blockIdx.x, tg = blockIdx.y;
    int tid = threadIdx.x, w = tid >> 5, lane = tid & 31;
#pragma unroll
    for (int i = 0; i < 8; i++)
        q[i][tid] = Q[((size_t)(tg * 8 + i) * NB + b) * NE + tid];
    __syncthreads();
    const float* MS = g_mem + ((size_t)tblS * NB * NM + (size_t)b * NM) * NE;
    for (int j = 0; j < 64; j++) {
        int m = w * 64 + j;
        const float* rowp = MS + (size_t)m * NE;
        float mv[8];
#pragma unroll
        for (int i = 0; i < 8; i++) mv[i] = rowp[i * 32 + lane];
#pragma unroll
        for (int t = 0; t < 8; t++) {
            float a = 0.f;
#pragma unroll
            for (int i = 0; i < 8; i++) a += mv[i] * q[t][i * 32 + lane];
#pragma unroll
            for (int off = 16; off; off >>= 1) a += __shfl_xor_sync(0xffffffffu, a, off);
            if (lane == 0) sc[t][m] = a;
        }
    }
    __syncthreads();
    {
        int t = w;
        float mx = -INFINITY;
#pragma unroll
        for (int i = 0; i < 16; i++) mx = fmaxf(mx, sc[t][i * 32 + lane]);
#pragma unroll
        for (int off = 16; off; off >>= 1) mx = fmaxf(mx, __shfl_xor_sync(0xffffffffu, mx, off));
        float ev[16], sum = 0.f;
#pragma unroll
        for (int i = 0; i < 16; i++) { ev[i] = expf(sc[t][i * 32 + lane] - mx); sum += ev[i]; }
#pragma unroll
        for (int off = 16; off; off >>= 1) sum += __shfl_xor_sync(0xffffffffu, sum, off);
        float inv = 1.0f / sum;
#pragma unroll
        for (int i = 0; i < 16; i++) sc[t][i * 32 + lane] = ev[i] * inv;
    }
    __syncthreads();
    const float* MA = g_mem + ((size_t)tblA * NB * NM + (size_t)b * NM) * NE;
    float acc[8] = {};
#pragma unroll 4
    for (int m = 0; m < NM; m++) {
        float mval = MA[(size_t)m * NE + tid];
#pragma unroll
        for (int t = 0; t < 8; t++) acc[t] += sc[t][m] * mval;
    }
#pragma unroll
    for (int t = 0; t < 8; t++)
        O[((size_t)(tg * 8 + t) * NB + b) * NE + tid] = acc[t];
}

// ---------------- decoder input embeddings ----------------
__global__ void k_xin(const int* __restrict__ tgt, const float* __restrict__ decC) {
    int tb = blockIdx.x;
    int t = tb / NB, b = tb % NB;
    int y = (t == 0) ? 2 : tgt[(t - 1) * NB + b];
    g_xin[(size_t)tb * NE + threadIdx.x] = decC[(size_t)y * NE + threadIdx.x];
}

// ---------------- register-tiled SGEMM (validated) for gi ----------------
__global__ __launch_bounds__(256, 2)
void k_sgemm(const float* __restrict__ A, const float* __restrict__ B,
             const float* __restrict__ bias, float* __restrict__ C,
             int M, int N, int K) {
    __shared__ float As[8][132];
    __shared__ float Bs[8][132];
    int tid = threadIdx.x;
    int m0 = blockIdx.y * 128, n0 = blockIdx.x * 128;
    int lr = tid >> 1;
    int lk = (tid & 1) * 4;
    const float* Ag = A + (size_t)(m0 + lr) * K + lk;
    const float* Bg = B + (size_t)(n0 + lr) * K + lk;
    int ty = tid >> 4, tx = tid & 15;
    float acc[8][8] = {};
    for (int k0 = 0; k0 < K; k0 += 8) {
        float4 av = *(const float4*)(Ag + k0);
        float4 bv = *(const float4*)(Bg + k0);
        As[lk + 0][lr] = av.x; As[lk + 1][lr] = av.y;
        As[lk + 2][lr] = av.z; As[lk + 3][lr] = av.w;
        Bs[lk + 0][lr] = bv.x; Bs[lk + 1][lr] = bv.y;
        Bs[lk + 2][lr] = bv.z; Bs[lk + 3][lr] = bv.w;
        __syncthreads();
#pragma unroll
        for (int kk = 0; kk < 8; kk++) {
            float a[8], b[8];
            *(float4*)&a[0] = *(const float4*)&As[kk][ty * 4];
            *(float4*)&a[4] = *(const float4*)&As[kk][64 + ty * 4];
            *(float4*)&b[0] = *(const float4*)&Bs[kk][tx * 4];
            *(float4*)&b[4] = *(const float4*)&Bs[kk][64 + tx * 4];
#pragma unroll
            for (int i = 0; i < 8; i++)
#pragma unroll
                for (int j = 0; j < 8; j++) acc[i][j] += a[i] * b[j];
        }
        __syncthreads();
    }
    float bb[8];
#pragma unroll
    for (int j = 0; j < 4; j++) {
        bb[j]     = bias[n0 + tx * 4 + j];
        bb[4 + j] = bias[n0 + 64 + tx * 4 + j];
    }
#pragma unroll
    for (int i = 0; i < 8; i++) {
        int m = m0 + ((i < 4) ? (ty * 4 + i) : (64 + ty * 4 + i - 4));
        float4 c0, c1;
        c0.x = acc[i][0] + bb[0]; c0.y = acc[i][1] + bb[1];
        c0.z = acc[i][2] + bb[2]; c0.w = acc[i][3] + bb[3];
        c1.x = acc[i][4] + bb[4]; c1.y = acc[i][5] + bb[5];
        c1.z = acc[i][6] + bb[6]; c1.w = acc[i][7] + bb[7];
        *(float4*)(C + (size_t)m * N + n0 + tx * 4) = c0;
        *(float4*)(C + (size_t)m * N + n0 + 64 + tx * 4) = c1;
    }
}

// ---------------- GRU v4: half2-paired coalesced W reads -----------------------
// Per k2, a warp reads one contiguous 128B line of g_Wt2; 128-iter inner loop.
__global__ void k_gru(const float* __restrict__ bhh, float* __restrict__ out_h) {
    __shared__ __align__(16) float h[NE];
    __shared__ float gh[NG];
    int b = blockIdx.x, tid = threadIdx.x;   // 768 threads, one gate row each
    if (tid < NE) h[tid] = g_q[b * NE + tid];
    float bias = bhh[tid];
    __syncthreads();
    const __half2* wp = g_Wt2 + tid;
    for (int t = 0; t < NT; t++) {
        float acc = bias;
#pragma unroll 16
        for (int k2 = 0; k2 < NE / 2; k2++) {
            float2 hh = *(const float2*)&h[k2 * 2];
            float2 wf = __half22float2(wp[(size_t)k2 * NG]);
            acc += wf.x * hh.x + wf.y * hh.y;
        }
        gh[tid] = acc;
        __syncthreads();
        if (tid < NE) {
            const float* gi = g_gi + ((size_t)t * NB + b) * NG;
            float r = 1.0f / (1.0f + expf(-(gi[tid] + gh[tid])));
            float z = 1.0f / (1.0f + expf(-(gi[NE + tid] + gh[NE + tid])));
            float n = tanhf(gi[2 * NE + tid] + r * gh[2 * NE + tid]);
            float hn = (1.0f - z) * n + z * h[tid];
            h[tid] = hn;
            g_H[((size_t)t * NB + b) * NE + tid] = hn;
            if (t == NT - 1) out_h[b * NE + tid] = hn;
        }
        __syncthreads();
    }
}

// ---------------- W_vocab -> fp16 (half2 vectorized) ----------------
__global__ void k_cvt_w(const float* __restrict__ W) {
    size_t i = ((size_t)blockIdx.x * 256 + threadIdx.x) * 2;
    float2 v = *(const float2*)(W + i);
    *(__half2*)(g_Wh + i) = __floats2half2_rn(v.x, v.y);
}

// ---------------- hop-0 fuse: qc = H+O0, X=[H|O0] -> fp16 ----------------
__global__ void k_fuse0() {
    int i = blockIdx.x * 256 + threadIdx.x;
    int e = i & (NE - 1);
    int tb = i >> 8;
    float hq = g_H[i], o = g_O[i];
    g_qc[i] = hq + o;
    size_t xi = (size_t)tb * KX + e;
    g_Xh[xi]      = __float2half_rn(hq);
    g_Xh[xi + NE] = __float2half_rn(o);
}

// ================ combined vocab GEMM + hop1/hop2 tail blocks ==================
#define MMAH16816(d, a, b) \
  asm volatile("mma.sync.aligned.m16n8k16.row.col.f32.f16.f16.f32 " \
    "{%0,%1,%2,%3}, {%4,%5,%6,%7}, {%8,%9}, {%0,%1,%2,%3};" \
    : "+f"(d[0]), "+f"(d[1]), "+f"(d[2]), "+f"(d[3]) \
    : "r"(a[0]), "r"(a[1]), "r"(a[2]), "r"(a[3]), "r"(b[0]), "r"(b[1]))

__device__ __forceinline__ void cp16(uint32_t dst, const void* src) {
    asm volatile("cp.async.cg.shared.global [%0], [%1], 16;\n" :: "r"(dst), "l"(src));
}

// hop1 + qc update + hop2 raw scores (validated R13)
__device__ void hop12_body(void* smraw, int bx, float* __restrict__ Sout) {
    float (*q)[NE]  = (float(*)[NE])smraw;
    float (*sc)[NM] = (float(*)[NM])((char*)smraw + 8 * NE * sizeof(float));
    int b = bx & (NB - 1), tg = bx >> 6;
    int tid = threadIdx.x, w = tid >> 5, lane = tid & 31;
#pragma unroll
    for (int i = 0; i < 8; i++)
        q[i][tid] = g_qc[((size_t)(tg * 8 + i) * NB + b) * NE + tid];
    __syncthreads();
    const float* MS = g_mem + ((size_t)4 * NB * NM + (size_t)b * NM) * NE;
    const float* MA = g_mem + ((size_t)5 * NB * NM + (size_t)b * NM) * NE;
    for (int j = 0; j < 64; j++) {
        int m = w * 64 + j;
        const float* rowp = MS + (size_t)m * NE;
        float mv[8];
#pragma unroll
        for (int i = 0; i < 8; i++) mv[i] = rowp[i * 32 + lane];
#pragma unroll
        for (int t = 0; t < 8; t++) {
            float a = 0.f;
#pragma unroll
            for (int i = 0; i < 8; i++) a += mv[i] * q[t][i * 32 + lane];
#pragma unroll
            for (int off = 16; off; off >>= 1) a += __shfl_xor_sync(0xffffffffu, a, off);
            if (lane == 0) sc[t][m] = a;
        }
    }
    __syncthreads();
    {
        int t = w;
        float mx = -INFINITY;
#pragma unroll
        for (int i = 0; i < 16; i++) mx = fmaxf(mx, sc[t][i * 32 + lane]);
#pragma unroll
        for (int off = 16; off; off >>= 1) mx = fmaxf(mx, __shfl_xor_sync(0xffffffffu, mx, off));
        float ev[16], sum = 0.f;
#pragma unroll
        for (int i = 0; i < 16; i++) { ev[i] = expf(sc[t][i * 32 + lane] - mx); sum += ev[i]; }
#pragma unroll
        for (int off = 16; off; off >>= 1) sum += __shfl_xor_sync(0xffffffffu, sum, off);
        float inv = 1.0f / sum;
#pragma unroll
        for (int i = 0; i < 16; i++) sc[t][i * 32 + lane] = ev[i] * inv;
    }
    __syncthreads();
    float acc[8] = {};
#pragma unroll 4
    for (int m = 0; m < NM; m++) {
        float mval = MA[(size_t)m * NE + tid];
#pragma unroll
        for (int t = 0; t < 8; t++) acc[t] += sc[t][m] * mval;
    }
    __syncthreads();
#pragma unroll
    for (int t = 0; t < 8; t++) q[t][tid] += acc[t];
    __syncthreads();
    for (int j = 0; j < 64; j++) {
        int m = w * 64 + j;
        const float* rowp = MA + (size_t)m * NE;
        float mv[8];
#pragma unroll
        for (int i = 0; i < 8; i++) mv[i] = rowp[i * 32 + lane];
#pragma unroll
        for (int t = 0; t < 8; t++) {
            float a = 0.f;
#pragma unroll
            for (int i = 0; i < 8; i++) a += mv[i] * q[t][i * 32 + lane];
#pragma unroll
            for (int off = 16; off; off >>= 1) a += __shfl_xor_sync(0xffffffffu, a, off);
            if (lane == 0) sc[t][m] = a;
        }
    }
    __syncthreads();
#pragma unroll
    for (int t = 0; t < 8; t++) {
        size_t row = (size_t)(tg * 8 + t) * NB + b;
        Sout[row * NM + tid]       = sc[t][tid];
        Sout[row * NM + 256 + tid] = sc[t][tid + 256];
    }
}

// grid (256, 17): y<16 & x<250 -> GEMM tile; y==16 -> hop12 block (x = b + 64*tg)
__global__ __launch_bounds__(256)
void k_hgemm_hop(const float* __restrict__ bias, float* __restrict__ C,
                 float* __restrict__ Sout) {
    __shared__ __align__(16) unsigned char sm[24576];
    if (blockIdx.y == 16) { hop12_body(sm, blockIdx.x, Sout); return; }
    if (blockIdx.x >= NV / 128) return;
    int tid = threadIdx.x;
    int n0 = blockIdx.x * 128, m0 = blockIdx.y * 128;
    int wid = tid >> 5, lane = tid & 31;
    int wm = (wid >> 2) * 64, wn = (wid & 3) * 32;
    int g = lane >> 2, tg = lane & 3;
    uint32_t sbase = (uint32_t)__cvta_generic_to_shared(sm);
    int lr = tid >> 1, lkc = tid & 1;

    const __half* srcA = g_Xh + (size_t)(m0 + lr) * KX + lkc * 8;
    const __half* srcB = g_Wh + (size_t)(n0 + lr) * KX + lkc * 8;
    uint32_t dbase = sbase + lr * 48 + lkc * 16;

    float acc[4][4][4] = {};

    cp16(dbase,        srcA);
    cp16(dbase + 6144, srcB);
    asm volatile("cp.async.commit_group;\n" ::);

    for (int it = 0; it < KX / 16; it++) {
        if (it + 1 < KX / 16) {
            uint32_t d2 = dbase + ((it + 1) & 1) * 12288;
            int koff = (it + 1) * 16;
            cp16(d2,        srcA + koff);
            cp16(d2 + 6144, srcB + koff);
            asm volatile("cp.async.commit_group;\n" ::);
            asm volatile("cp.async.wait_group 1;\n" ::);
        } else {
            asm volatile("cp.async.wait_group 0;\n" ::);
        }
        __syncthreads();
        const char* sb = (const char*)sm + (it & 1) * 12288;
        const __half* Ah = (const __half*)(sb);
        const __half* Bh = (const __half*)(sb + 6144);
        uint32_t ah[4][4];
        int c = tg * 2;
#pragma unroll
        for (int f = 0; f < 4; f++) {
            int r = wm + f * 16 + g;
            ah[f][0] = *(const uint32_t*)&Ah[r * 24 + c];
            ah[f][1] = *(const uint32_t*)&Ah[(r + 8) * 24 + c];
            ah[f][2] = *(const uint32_t*)&Ah[r * 24 + c + 8];
            ah[f][3] = *(const uint32_t*)&Ah[(r + 8) * 24 + c + 8];
        }
#pragma unroll
        for (int fn = 0; fn < 4; fn++) {
            int r = wn + fn * 8 + g;
            uint32_t bh[2];
            bh[0] = *(const uint32_t*)&Bh[r * 24 + c];
            bh[1] = *(const uint32_t*)&Bh[r * 24 + c + 8];
#pragma unroll
            for (int f = 0; f < 4; f++)
                MMAH16816(acc[f][fn], ah[f], bh);
        }
        __syncthreads();
    }
#pragma unroll
    for (int f = 0; f < 4; f++) {
        int rbase = m0 + wm + f * 16 + g;
#pragma unroll
        for (int fn = 0; fn < 4; fn++) {
            int c0 = n0 + wn + fn * 8 + tg * 2;
            float b0v = bias[c0], b1v = bias[c0 + 1];
            float2 v0 = {acc[f][fn][0] + b0v, acc[f][fn][1] + b1v};
            float2 v1 = {acc[f][fn][2] + b0v, acc[f][fn][3] + b1v};
            *(float2*)(C + (size_t)rbase * NV + c0) = v0;
            *(float2*)(C + (size_t)(rbase + 8) * NV + c0) = v1;
        }
    }
}

// ---------------- launch ----------------
extern "C" void kernel_launch(void* const* d_in, const int* in_sizes, int n_in,
                              void* d_out, int out_size) {
    const int*   inp    = (const int*)d_in[0];
    const int*   tgt    = (const int*)d_in[1];
    const float* encC   = (const float*)d_in[2];
    const float* decC   = (const float*)d_in[3];
    const float* W_ih   = (const float*)d_in[4];
    const float* W_hh   = (const float*)d_in[5];
    const float* b_ih   = (const float*)d_in[6];
    const float* b_hh   = (const float*)d_in[7];
    const float* W_voc  = (const float*)d_in[8];
    const float* b_voc  = (const float*)d_in[9];
    float* out = (float*)d_out;

    float *gq, *gO, *gH, *gxin, *ggi;
    cudaGetSymbolAddress((void**)&gq,    g_q);
    cudaGetSymbolAddress((void**)&gO,    g_O);
    cudaGetSymbolAddress((void**)&gH,    g_H);
    cudaGetSymbolAddress((void**)&gxin,  g_xin);
    cudaGetSymbolAddress((void**)&ggi,   g_gi);

    // dependency-free setup
    k_cvt_w<<<(unsigned)(((size_t)NV * KX) / 512), 256>>>(W_voc);
    k_whh_t<<<dim3(NG / 32, NE / 32), dim3(32, 32)>>>(W_hh);
    k_xin<<<NT * NB, NE>>>(tgt, decC);
    k_embed<<<(unsigned)((6ull * NB * NM * 64) / 256), 256>>>(inp, encC, decC);

    // ---- encoder ----
    k_mean<<<NB, 256>>>();
    k_hop_enc<<<NB, 1024>>>(gq, 0, 1, gq);
    k_hop_enc<<<NB, 1024>>>(gq, 1, 2, gq);

    // ---- decoder setup + GRU (half2-paired W) ----
    k_sgemm<<<dim3(NG / 128, (NT * NB) / 128), 256>>>(gxin, W_ih, b_ih, ggi, NT * NB, NG, NE);
    k_gru<<<NB, NG>>>(b_hh, out + OUT_H);

    // ---- decoder hop 0 -> O0; build qc and fp16 X ----
    k_hop_dec<<<dim3(NB, NT / 8), 256>>>(gH, 3, 4, gO);
    k_fuse0<<<(NT * NB * NE) / 256, 256>>>();

    // ---- vocab GEMM + hop1/hop2 tail blocks ----
    k_hgemm_hop<<<dim3(256, 17), 256>>>(b_voc, out, out + OUT_PTR);
}

// round 16
// speedup vs baseline: 1.3084x; 1.1122x over previous
#include <cuda_runtime.h>
#include <cuda_fp16.h>
#include <math.h>
#include <stdint.h>

// Problem constants
#define NB   64      // batch
#define NM   512     // memory slots
#define NE   256     // embedding dim
#define NT   32      // decode steps
#define NV   32000   // vocab
#define NTR  4       // tokens per memory slot
#define NG   768     // 3*NE gate dim
#define KX   512     // 2*NE vocab-GEMM K

// Output layout: [T,B,V] vocab | [T,B,M] ptr | [1,B,E] h
#define OUT_PTR  ((size_t)NT*NB*NV)
#define OUT_H    (OUT_PTR + (size_t)NT*NB*NM)

// ---------------- scratch ----------------
__device__ float g_mem[6ull*NB*NM*NE];   // 201 MB
__device__ float g_q  [NB*NE];
__device__ float g_H  [(size_t)NT*NB*NE];
__device__ float g_xin[(size_t)NT*NB*NE];
__device__ float g_gi [(size_t)NT*NB*NG];
__device__ float g_qc [(size_t)NT*NB*NE];
__device__ uint2 g_Wt4[(size_t)(NE/4)*NG];   // W_hh: 4 k-values (2xhalf2) per entry
__device__ __half g_Wh[(size_t)NV*KX];
__device__ __half g_Xh[(size_t)NT*NB*KX];

// ---------------- 1) embedding sums (float4, validated @74us) ------------------
__global__ void k_embed(const int* __restrict__ inp,
                        const float* __restrict__ encC,
                        const float* __restrict__ decC) {
    size_t idx = (size_t)blockIdx.x * 256 + threadIdx.x;  // over 6*NB*NM*64
    int e4  = (int)(idx & 63);
    size_t r = idx >> 6;
    int bm  = (int)(r % (NB * NM));
    int tbl = (int)(r / (NB * NM));
    int b = bm / NM, m = bm % NM;
    const float* tab = (tbl < 3) ? (encC + (size_t)(tbl + 1) * NV * NE)
                                 : (decC + (size_t)(tbl - 3) * NV * NE);
    const float4* tab4 = (const float4*)tab;
    const int* ix = inp + ((size_t)m * NB + b) * NTR;
    float4 s = {0.f, 0.f, 0.f, 0.f};
    for (int tr = 0; tr < NTR; tr++) {
        float4 v = tab4[(size_t)ix[tr] * 64 + e4];
        s.x += v.x; s.y += v.y; s.z += v.z; s.w += v.w;
    }
    ((float4*)g_mem)[((size_t)tbl * NB * NM + bm) * 64 + e4] = s;
}

// ---------------- W_hh transpose -> 4-k packed (2xhalf2) layout ----------------
__global__ void k_whh_t(const float* __restrict__ W) {
    __shared__ float t[32][33];
    int j0 = blockIdx.x * 32, k0 = blockIdx.y * 32;
    t[threadIdx.y][threadIdx.x] = W[(size_t)(j0 + threadIdx.y) * NE + k0 + threadIdx.x];
    __syncthreads();
    if (threadIdx.y < 8) {
        int kl = threadIdx.y * 4;
        __half2 lo = __floats2half2_rn(t[threadIdx.x][kl],     t[threadIdx.x][kl + 1]);
        __half2 hi = __floats2half2_rn(t[threadIdx.x][kl + 2], t[threadIdx.x][kl + 3]);
        uint2 v;
        v.x = *(uint32_t*)&lo;
        v.y = *(uint32_t*)&hi;
        g_Wt4[(size_t)((k0 + kl) >> 2) * NG + j0 + threadIdx.x] = v;
    }
}

// ---------------- encoder: mean + 2 hops fused, one block per b ----------------
__device__ __forceinline__ void enc_hop(float* q, float* sc, float* red,
                                        float (*part)[NE],
                                        const float* MS, const float* MA) {
    int tid = threadIdx.x, w = tid >> 5, lane = tid & 31;
    for (int j = 0; j < 16; j++) {
        int m = w * 16 + j;
        const float* rowp = MS + (size_t)m * NE;
        float a = 0.f;
#pragma unroll
        for (int i = 0; i < 8; i++) a += rowp[i * 32 + lane] * q[i * 32 + lane];
#pragma unroll
        for (int off = 16; off; off >>= 1) a += __shfl_xor_sync(0xffffffffu, a, off);
        if (lane == 0) sc[m] = a;
    }
    __syncthreads();
    float v = 0.f, e = 0.f;
    if (tid < 512) {
        v = sc[tid];
        float mx = v;
#pragma unroll
        for (int off = 16; off; off >>= 1) mx = fmaxf(mx, __shfl_xor_sync(0xffffffffu, mx, off));
        if (lane == 0) red[w] = mx;
    }
    __syncthreads();
    if (tid == 0) {
        float m8 = red[0];
        for (int i = 1; i < 16; i++) m8 = fmaxf(m8, red[i]);
        red[32] = m8;
    }
    __syncthreads();
    if (tid < 512) {
        e = expf(v - red[32]);
        float s = e;
#pragma unroll
        for (int off = 16; off; off >>= 1) s += __shfl_xor_sync(0xffffffffu, s, off);
        if (lane == 0) red[16 + w] = s;
    }
    __syncthreads();
    if (tid == 0) {
        float t = 0.f;
        for (int i = 0; i < 16; i++) t += red[16 + i];
        red[33] = t;
    }
    __syncthreads();
    if (tid < 512) sc[tid] = e * (1.0f / red[33]);
    __syncthreads();
    int qd = tid >> 8, ee = tid & 255;
    float acc = 0.f;
#pragma unroll 4
    for (int m = qd * 128; m < qd * 128 + 128; m++)
        acc += sc[m] * MA[(size_t)m * NE + ee];
    part[qd][ee] = acc;
    __syncthreads();
    if (tid < NE)
        q[tid] += part[0][tid] + part[1][tid] + part[2][tid] + part[3][tid];
    __syncthreads();
}

__global__ void k_enc() {
    __shared__ float q[NE];
    __shared__ float sc[NM];
    __shared__ float red[40];
    __shared__ float part[4][NE];
    int b = blockIdx.x;
    int tid = threadIdx.x;   // 1024 threads
    const float* T0 = g_mem + ((size_t)0 * NB * NM + (size_t)b * NM) * NE;
    const float* T1 = g_mem + ((size_t)1 * NB * NM + (size_t)b * NM) * NE;
    const float* T2 = g_mem + ((size_t)2 * NB * NM + (size_t)b * NM) * NE;
    // hop0: uniform attention = mean over m of table 0 (4-way m split)
    {
        int qd = tid >> 8, ee = tid & 255;
        float acc = 0.f;
#pragma unroll 4
        for (int m = qd * 128; m < qd * 128 + 128; m++)
            acc += T0[(size_t)m * NE + ee];
        part[qd][ee] = acc;
        __syncthreads();
        if (tid < NE)
            q[tid] = (part[0][tid] + part[1][tid] + part[2][tid] + part[3][tid])
                     * (1.0f / NM);
        __syncthreads();
    }
    enc_hop(q, sc, red, part, T0, T1);   // hop 1
    enc_hop(q, sc, red, part, T1, T2);   // hop 2
    if (tid < NE) g_q[b * NE + tid] = q[tid];
}

// ---------------- decoder hop 0 + fuse0 (writes qc and fp16 X directly) --------
__global__ void k_hop_dec(const float* __restrict__ Q) {
    __shared__ float q[8][NE];
    __shared__ float sc[8][NM];
    int b = blockIdx.x, tg = blockIdx.y;
    int tid = threadIdx.x, w = tid >> 5, lane = tid & 31;
#pragma unroll
    for (int i = 0; i < 8; i++)
        q[i][tid] = Q[((size_t)(tg * 8 + i) * NB + b) * NE + tid];
    __syncthreads();
    const float* MS = g_mem + ((size_t)3 * NB * NM + (size_t)b * NM) * NE;
    for (int j = 0; j < 64; j++) {
        int m = w * 64 + j;
        const float* rowp = MS + (size_t)m * NE;
        float mv[8];
#pragma unroll
        for (int i = 0; i < 8; i++) mv[i] = rowp[i * 32 + lane];
#pragma unroll
        for (int t = 0; t < 8; t++) {
            float a = 0.f;
#pragma unroll
            for (int i = 0; i < 8; i++) a += mv[i] * q[t][i * 32 + lane];
#pragma unroll
            for (int off = 16; off; off >>= 1) a += __shfl_xor_sync(0xffffffffu, a, off);
            if (lane == 0) sc[t][m] = a;
        }
    }
    __syncthreads();
    {
        int t = w;
        float mx = -INFINITY;
#pragma unroll
        for (int i = 0; i < 16; i++) mx = fmaxf(mx, sc[t][i * 32 + lane]);
#pragma unroll
        for (int off = 16; off; off >>= 1) mx = fmaxf(mx, __shfl_xor_sync(0xffffffffu, mx, off));
        float ev[16], sum = 0.f;
#pragma unroll
        for (int i = 0; i < 16; i++) { ev[i] = expf(sc[t][i * 32 + lane] - mx); sum += ev[i]; }
#pragma unroll
        for (int off = 16; off; off >>= 1) sum += __shfl_xor_sync(0xffffffffu, sum, off);
        float inv = 1.0f / sum;
#pragma unroll
        for (int i = 0; i < 16; i++) sc[t][i * 32 + lane] = ev[i] * inv;
    }
    __syncthreads();
    const float* MA = g_mem + ((size_t)4 * NB * NM + (size_t)b * NM) * NE;
    float acc[8] = {};
#pragma unroll 4
    for (int m = 0; m < NM; m++) {
        float mval = MA[(size_t)m * NE + tid];
#pragma unroll
        for (int t = 0; t < 8; t++) acc[t] += sc[t][m] * mval;
    }
#pragma unroll
    for (int t = 0; t < 8; t++) {
        size_t row = (size_t)(tg * 8 + t) * NB + b;
        float hq = q[t][tid], o = acc[t];
        g_qc[row * NE + tid] = hq + o;
        g_Xh[row * KX + tid]      = __float2half_rn(hq);
        g_Xh[row * KX + NE + tid] = __float2half_rn(o);
    }
}

// ---------------- decoder input embeddings ----------------
__global__ void k_xin(const int* __restrict__ tgt, const float* __restrict__ decC) {
    int tb = blockIdx.x;
    int t = tb / NB, b = tb % NB;
    int y = (t == 0) ? 2 : tgt[(t - 1) * NB + b];
    g_xin[(size_t)tb * NE + threadIdx.x] = decC[(size_t)y * NE + threadIdx.x];
}

// ---------------- register-tiled SGEMM (validated) for gi ----------------
__global__ __launch_bounds__(256, 2)
void k_sgemm(const float* __restrict__ A, const float* __restrict__ B,
             const float* __restrict__ bias, float* __restrict__ C,
             int M, int N, int K) {
    __shared__ float As[8][132];
    __shared__ float Bs[8][132];
    int tid = threadIdx.x;
    int m0 = blockIdx.y * 128, n0 = blockIdx.x * 128;
    int lr = tid >> 1;
    int lk = (tid & 1) * 4;
    const float* Ag = A + (size_t)(m0 + lr) * K + lk;
    const float* Bg = B + (size_t)(n0 + lr) * K + lk;
    int ty = tid >> 4, tx = tid & 15;
    float acc[8][8] = {};
    for (int k0 = 0; k0 < K; k0 += 8) {
        float4 av = *(const float4*)(Ag + k0);
        float4 bv = *(const float4*)(Bg + k0);
        As[lk + 0][lr] = av.x; As[lk + 1][lr] = av.y;
        As[lk + 2][lr] = av.z; As[lk + 3][lr] = av.w;
        Bs[lk + 0][lr] = bv.x; Bs[lk + 1][lr] = bv.y;
        Bs[lk + 2][lr] = bv.z; Bs[lk + 3][lr] = bv.w;
        __syncthreads();
#pragma unroll
        for (int kk = 0; kk < 8; kk++) {
            float a[8], b[8];
            *(float4*)&a[0] = *(const float4*)&As[kk][ty * 4];
            *(float4*)&a[4] = *(const float4*)&As[kk][64 + ty * 4];
            *(float4*)&b[0] = *(const float4*)&Bs[kk][tx * 4];
            *(float4*)&b[4] = *(const float4*)&Bs[kk][64 + tx * 4];
#pragma unroll
            for (int i = 0; i < 8; i++)
#pragma unroll
                for (int j = 0; j < 8; j++) acc[i][j] += a[i] * b[j];
        }
        __syncthreads();
    }
    float bb[8];
#pragma unroll
    for (int j = 0; j < 4; j++) {
        bb[j]     = bias[n0 + tx * 4 + j];
        bb[4 + j] = bias[n0 + 64 + tx * 4 + j];
    }
#pragma unroll
    for (int i = 0; i < 8; i++) {
        int m = m0 + ((i < 4) ? (ty * 4 + i) : (64 + ty * 4 + i - 4));
        float4 c0, c1;
        c0.x = acc[i][0] + bb[0]; c0.y = acc[i][1] + bb[1];
        c0.z = acc[i][2] + bb[2]; c0.w = acc[i][3] + bb[3];
        c1.x = acc[i][4] + bb[4]; c1.y = acc[i][5] + bb[5];
        c1.z = acc[i][6] + bb[6]; c1.w = acc[i][7] + bb[7];
        *(float4*)(C + (size_t)m * N + n0 + tx * 4) = c0;
        *(float4*)(C + (size_t)m * N + n0 + 64 + tx * 4) = c1;
    }
}

// ---------------- GRU v5: 4-k packed W (LDG.64 + LDS.128 per 4 k) --------------
__global__ void k_gru(const float* __restrict__ bhh, float* __restrict__ out_h) {
    __shared__ __align__(16) float h[NE];
    __shared__ float gh[NG];
    int b = blockIdx.x, tid = threadIdx.x;   // 768 threads, one gate row each
    if (tid < NE) h[tid] = g_q[b * NE + tid];
    float bias = bhh[tid];
    __syncthreads();
    const uint2* wp = g_Wt4 + tid;
    for (int t = 0; t < NT; t++) {
        float acc = bias;
#pragma unroll 16
        for (int k4 = 0; k4 < NE / 4; k4++) {
            uint2 wv = wp[(size_t)k4 * NG];
            float2 w01 = __half22float2(*(__half2*)&wv.x);
            float2 w23 = __half22float2(*(__half2*)&wv.y);
            float4 hh = *(const float4*)&h[k4 * 4];
            acc += w01.x * hh.x + w01.y * hh.y + w23.x * hh.z + w23.y * hh.w;
        }
        gh[tid] = acc;
        __syncthreads();
        if (tid < NE) {
            const float* gi = g_gi + ((size_t)t * NB + b) * NG;
            float r = 1.0f / (1.0f + expf(-(gi[tid] + gh[tid])));
            float z = 1.0f / (1.0f + expf(-(gi[NE + tid] + gh[NE + tid])));
            float n = tanhf(gi[2 * NE + tid] + r * gh[2 * NE + tid]);
            float hn = (1.0f - z) * n + z * h[tid];
            h[tid] = hn;
            g_H[((size_t)t * NB + b) * NE + tid] = hn;
            if (t == NT - 1) out_h[b * NE + tid] = hn;
        }
        __syncthreads();
    }
}

// ---------------- W_vocab -> fp16 (float4 -> 2x half2) ----------------
__global__ void k_cvt_w(const float* __restrict__ W) {
    size_t i = ((size_t)blockIdx.x * 256 + threadIdx.x) * 4;
    float4 v = *(const float4*)(W + i);
    __half2 lo = __floats2half2_rn(v.x, v.y);
    __half2 hi = __floats2half2_rn(v.z, v.w);
    uint2 o;
    o.x = *(uint32_t*)&lo;
    o.y = *(uint32_t*)&hi;
    *(uint2*)(g_Wh + i) = o;
}

// ================ combined vocab GEMM + hop1/hop2 front blocks =================
#define MMAH16816(d, a, b) \
  asm volatile("mma.sync.aligned.m16n8k16.row.col.f32.f16.f16.f32 " \
    "{%0,%1,%2,%3}, {%4,%5,%6,%7}, {%8,%9}, {%0,%1,%2,%3};" \
    : "+f"(d[0]), "+f"(d[1]), "+f"(d[2]), "+f"(d[3]) \
    : "r"(a[0]), "r"(a[1]), "r"(a[2]), "r"(a[3]), "r"(b[0]), "r"(b[1]))

__device__ __forceinline__ void cp16(uint32_t dst, const void* src) {
    asm volatile("cp.async.cg.shared.global [%0], [%1], 16;\n" :: "r"(dst), "l"(src));
}

// hop1 + qc update + hop2 raw scores (validated R13/R14)
__device__ void hop12_body(void* smraw, int bx, float* __restrict__ Sout) {
    float (*q)[NE]  = (float(*)[NE])smraw;
    float (*sc)[NM] = (float(*)[NM])((char*)smraw + 8 * NE * sizeof(float));
    int b = bx & (NB - 1), tg = bx >> 6;
    int tid = threadIdx.x, w = tid >> 5, lane = tid & 31;
#pragma unroll
    for (int i = 0; i < 8; i++)
        q[i][tid] = g_qc[((size_t)(tg * 8 + i) * NB + b) * NE + tid];
    __syncthreads();
    const float* MS = g_mem + ((size_t)4 * NB * NM + (size_t)b * NM) * NE;
    const float* MA = g_mem + ((size_t)5 * NB * NM + (size_t)b * NM) * NE;
    for (int j = 0; j < 64; j++) {
        int m = w * 64 + j;
        const float* rowp = MS + (size_t)m * NE;
        float mv[8];
#pragma unroll
        for (int i = 0; i < 8; i++) mv[i] = rowp[i * 32 + lane];
#pragma unroll
        for (int t = 0; t < 8; t++) {
            float a = 0.f;
#pragma unroll
            for (int i = 0; i < 8; i++) a += mv[i] * q[t][i * 32 + lane];
#pragma unroll
            for (int off = 16; off; off >>= 1) a += __shfl_xor_sync(0xffffffffu, a, off);
            if (lane == 0) sc[t][m] = a;
        }
    }
    __syncthreads();
    {
        int t = w;
        float mx = -INFINITY;
#pragma unroll
        for (int i = 0; i < 16; i++) mx = fmaxf(mx, sc[t][i * 32 + lane]);
#pragma unroll
        for (int off = 16; off; off >>= 1) mx = fmaxf(mx, __shfl_xor_sync(0xffffffffu, mx, off));
        float ev[16], sum = 0.f;
#pragma unroll
        for (int i = 0; i < 16; i++) { ev[i] = expf(sc[t][i * 32 + lane] - mx); sum += ev[i]; }
#pragma unroll
        for (int off = 16; off; off >>= 1) sum += __shfl_xor_sync(0xffffffffu, sum, off);
        float inv = 1.0f / sum;
#pragma unroll
        for (int i = 0; i < 16; i++) sc[t][i * 32 + lane] = ev[i] * inv;
    }
    __syncthreads();
    float acc[8] = {};
#pragma unroll 4
    for (int m = 0; m < NM; m++) {
        float mval = MA[(size_t)m * NE + tid];
#pragma unroll
        for (int t = 0; t < 8; t++) acc[t] += sc[t][m] * mval;
    }
    __syncthreads();
#pragma unroll
    for (int t = 0; t < 8; t++) q[t][tid] += acc[t];
    __syncthreads();
    for (int j = 0; j < 64; j++) {
        int m = w * 64 + j;
        const float* rowp = MA + (size_t)m * NE;
        float mv[8];
#pragma unroll
        for (int i = 0; i < 8; i++) mv[i] = rowp[i * 32 + lane];
#pragma unroll
        for (int t = 0; t < 8; t++) {
            float a = 0.f;
#pragma unroll
            for (int i = 0; i < 8; i++) a += mv[i] * q[t][i * 32 + lane];
#pragma unroll
            for (int off = 16; off; off >>= 1) a += __shfl_xor_sync(0xffffffffu, a, off);
            if (lane == 0) sc[t][m] = a;
        }
    }
    __syncthreads();
#pragma unroll
    for (int t = 0; t < 8; t++) {
        size_t row = (size_t)(tg * 8 + t) * NB + b;
        Sout[row * NM + tid]       = sc[t][tid];
        Sout[row * NM + 256 + tid] = sc[t][tid + 256];
    }
}

// grid (256, 17): y==0 -> hop12 (front wave, overlaps GEMM); y>=1 -> GEMM tile
__global__ __launch_bounds__(256)
void k_hgemm_hop(const float* __restrict__ bias, float* __restrict__ C,
                 float* __restrict__ Sout) {
    __shared__ __align__(16) unsigned char sm[24576];
    if (blockIdx.y == 0) { hop12_body(sm, blockIdx.x, Sout); return; }
    if (blockIdx.x >= NV / 128) return;
    int tid = threadIdx.x;
    int n0 = blockIdx.x * 128, m0 = (blockIdx.y - 1) * 128;
    int wid = tid >> 5, lane = tid & 31;
    int wm = (wid >> 2) * 64, wn = (wid & 3) * 32;
    int g = lane >> 2, tg = lane & 3;
    uint32_t sbase = (uint32_t)__cvta_generic_to_shared(sm);
    int lr = tid >> 1, lkc = tid & 1;

    const __half* srcA = g_Xh + (size_t)(m0 + lr) * KX + lkc * 8;
    const __half* srcB = g_Wh + (size_t)(n0 + lr) * KX + lkc * 8;
    uint32_t dbase = sbase + lr * 48 + lkc * 16;

    float acc[4][4][4] = {};

    cp16(dbase,        srcA);
    cp16(dbase + 6144, srcB);
    asm volatile("cp.async.commit_group;\n" ::);

    for (int it = 0; it < KX / 16; it++) {
        if (it + 1 < KX / 16) {
            uint32_t d2 = dbase + ((it + 1) & 1) * 12288;
            int koff = (it + 1) * 16;
            cp16(d2,        srcA + koff);
            cp16(d2 + 6144, srcB + koff);
            asm volatile("cp.async.commit_group;\n" ::);
            asm volatile("cp.async.wait_group 1;\n" ::);
        } else {
            asm volatile("cp.async.wait_group 0;\n" ::);
        }
        __syncthreads();
        const char* sb = (const char*)sm + (it & 1) * 12288;
        const __half* Ah = (const __half*)(sb);
        const __half* Bh = (const __half*)(sb + 6144);
        uint32_t ah[4][4];
        int c = tg * 2;
#pragma unroll
        for (int f = 0; f < 4; f++) {
            int r = wm + f * 16 + g;
            ah[f][0] = *(const uint32_t*)&Ah[r * 24 + c];
            ah[f][1] = *(const uint32_t*)&Ah[(r + 8) * 24 + c];
            ah[f][2] = *(const uint32_t*)&Ah[r * 24 + c + 8];
            ah[f][3] = *(const uint32_t*)&Ah[(r + 8) * 24 + c + 8];
        }
#pragma unroll
        for (int fn = 0; fn < 4; fn++) {
            int r = wn + fn * 8 + g;
            uint32_t bh[2];
            bh[0] = *(const uint32_t*)&Bh[r * 24 + c];
            bh[1] = *(const uint32_t*)&Bh[r * 24 + c + 8];
#pragma unroll
            for (int f = 0; f < 4; f++)
                MMAH16816(acc[f][fn], ah[f], bh);
        }
        __syncthreads();
    }
#pragma unroll
    for (int f = 0; f < 4; f++) {
        int rbase = m0 + wm + f * 16 + g;
#pragma unroll
        for (int fn = 0; fn < 4; fn++) {
            int c0 = n0 + wn + fn * 8 + tg * 2;
            float b0v = bias[c0], b1v = bias[c0 + 1];
            float2 v0 = {acc[f][fn][0] + b0v, acc[f][fn][1] + b1v};
            float2 v1 = {acc[f][fn][2] + b0v, acc[f][fn][3] + b1v};
            *(float2*)(C + (size_t)rbase * NV + c0) = v0;
            *(float2*)(C + (size_t)(rbase + 8) * NV + c0) = v1;
        }
    }
}

// ---------------- launch ----------------
extern "C" void kernel_launch(void* const* d_in, const int* in_sizes, int n_in,
                              void* d_out, int out_size) {
    const int*   inp    = (const int*)d_in[0];
    const int*   tgt    = (const int*)d_in[1];
    const float* encC   = (const float*)d_in[2];
    const float* decC   = (const float*)d_in[3];
    const float* W_ih   = (const float*)d_in[4];
    const float* W_hh   = (const float*)d_in[5];
    const float* b_ih   = (const float*)d_in[6];
    const float* b_hh   = (const float*)d_in[7];
    const float* W_voc  = (const float*)d_in[8];
    const float* b_voc  = (const float*)d_in[9];
    float* out = (float*)d_out;

    float *gH, *gxin, *ggi;
    cudaGetSymbolAddress((void**)&gH,   g_H);
    cudaGetSymbolAddress((void**)&gxin, g_xin);
    cudaGetSymbolAddress((void**)&ggi,  g_gi);

    // dependency-free setup
    k_cvt_w<<<(unsigned)(((size_t)NV * KX) / 1024), 256>>>(W_voc);
    k_whh_t<<<dim3(NG / 32, NE / 32), dim3(32, 32)>>>(W_hh);
    k_xin<<<NT * NB, NE>>>(tgt, decC);
    k_embed<<<(unsigned)((6ull * NB * NM * 64) / 256), 256>>>(inp, encC, decC);

    // ---- encoder: mean + 2 hops fused ----
    k_enc<<<NB, 1024>>>();

    // ---- decoder setup + GRU ----
    k_sgemm<<<dim3(NG / 128, (NT * NB) / 128), 256>>>(gxin, W_ih, b_ih, ggi, NT * NB, NG, NE);
    k_gru<<<NB, NG>>>(b_hh, out + OUT_H);

    // ---- decoder hop 0 (fused fuse0: writes qc + fp16 X) ----
    k_hop_dec<<<dim3(NB, NT / 8), 256>>>(gH);

    // ---- vocab GEMM + hop1/hop2 front blocks ----
    k_hgemm_hop<<<dim3(256, 17), 256>>>(b_voc, out, out + OUT_PTR);
}

// round 17
// speedup vs baseline: 1.3496x; 1.0315x over previous
#include <cuda_runtime.h>
#include <cuda_fp16.h>
#include <math.h>
#include <stdint.h>

// Problem constants
#define NB   64      // batch
#define NM   512     // memory slots
#define NE   256     // embedding dim
#define NT   32      // decode steps
#define NV   32000   // vocab
#define NTR  4       // tokens per memory slot
#define NG   768     // 3*NE gate dim
#define KX   512     // 2*NE vocab-GEMM K

// Output layout: [T,B,V] vocab | [T,B,M] ptr | [1,B,E] h
#define OUT_PTR  ((size_t)NT*NB*NV)
#define OUT_H    (OUT_PTR + (size_t)NT*NB*NM)

// ---------------- scratch ----------------
__device__ float g_mem[6ull*NB*NM*NE];   // 201 MB
__device__ float g_q  [NB*NE];
__device__ float g_H  [(size_t)NT*NB*NE];
__device__ float g_xin[(size_t)NT*NB*NE];
__device__ float g_gi [(size_t)NT*NB*NG];
__device__ float g_qc [(size_t)NT*NB*NE];
__device__ uint2 g_Wt4[(size_t)(NE/4)*NG];   // W_hh: 4 k-values (2xhalf2) per entry
__device__ __half g_Wh[(size_t)NV*KX];
__device__ __half g_Xh[(size_t)NT*NB*KX];

// ---------------- fused setup: embed + cvt_w + xin (block-range dispatch) ------
#define NBLK_EMBED  49152            // 6*NB*NM*64 / 256
#define NBLK_CVTW   16000            // NV*KX / 1024
#define NBLK_XIN    (NT*NB)          // 2048
__global__ void k_setup(const int* __restrict__ inp,
                        const float* __restrict__ encC,
                        const float* __restrict__ decC,
                        const float* __restrict__ Wv,
                        const int* __restrict__ tgt) {
    int bid = blockIdx.x;
    int tid = threadIdx.x;
    if (bid < NBLK_EMBED) {
        // embedding sums (float4, validated @74us)
        size_t idx = (size_t)bid * 256 + tid;
        int e4  = (int)(idx & 63);
        size_t r = idx >> 6;
        int bm  = (int)(r % (NB * NM));
        int tbl = (int)(r / (NB * NM));
        int b = bm / NM, m = bm % NM;
        const float* tab = (tbl < 3) ? (encC + (size_t)(tbl + 1) * NV * NE)
                                     : (decC + (size_t)(tbl - 3) * NV * NE);
        const float4* tab4 = (const float4*)tab;
        const int* ix = inp + ((size_t)m * NB + b) * NTR;
        float4 s = {0.f, 0.f, 0.f, 0.f};
        for (int tr = 0; tr < NTR; tr++) {
            float4 v = tab4[(size_t)ix[tr] * 64 + e4];
            s.x += v.x; s.y += v.y; s.z += v.z; s.w += v.w;
        }
        ((float4*)g_mem)[((size_t)tbl * NB * NM + bm) * 64 + e4] = s;
    } else if (bid < NBLK_EMBED + NBLK_CVTW) {
        // W_vocab -> fp16 (float4 -> 2x half2)
        size_t i = (((size_t)(bid - NBLK_EMBED)) * 256 + tid) * 4;
        float4 v = *(const float4*)(Wv + i);
        __half2 lo = __floats2half2_rn(v.x, v.y);
        __half2 hi = __floats2half2_rn(v.z, v.w);
        uint2 o;
        o.x = *(uint32_t*)&lo;
        o.y = *(uint32_t*)&hi;
        *(uint2*)(g_Wh + i) = o;
    } else {
        // decoder input embeddings (teacher forcing)
        int tb = bid - NBLK_EMBED - NBLK_CVTW;
        int t = tb / NB, b = tb % NB;
        int y = (t == 0) ? 2 : tgt[(t - 1) * NB + b];
        g_xin[(size_t)tb * NE + tid] = decC[(size_t)y * NE + tid];
    }
}

// ---------------- W_hh transpose -> 4-k packed (2xhalf2) layout ----------------
__global__ void k_whh_t(const float* __restrict__ W) {
    __shared__ float t[32][33];
    int j0 = blockIdx.x * 32, k0 = blockIdx.y * 32;
    t[threadIdx.y][threadIdx.x] = W[(size_t)(j0 + threadIdx.y) * NE + k0 + threadIdx.x];
    __syncthreads();
    if (threadIdx.y < 8) {
        int kl = threadIdx.y * 4;
        __half2 lo = __floats2half2_rn(t[threadIdx.x][kl],     t[threadIdx.x][kl + 1]);
        __half2 hi = __floats2half2_rn(t[threadIdx.x][kl + 2], t[threadIdx.x][kl + 3]);
        uint2 v;
        v.x = *(uint32_t*)&lo;
        v.y = *(uint32_t*)&hi;
        g_Wt4[(size_t)((k0 + kl) >> 2) * NG + j0 + threadIdx.x] = v;
    }
}

// ---------------- encoder: mean + 2 hops fused (validated R16) -----------------
__device__ __forceinline__ void enc_hop(float* q, float* sc, float* red,
                                        float (*part)[NE],
                                        const float* MS, const float* MA) {
    int tid = threadIdx.x, w = tid >> 5, lane = tid & 31;
    for (int j = 0; j < 16; j++) {
        int m = w * 16 + j;
        const float* rowp = MS + (size_t)m * NE;
        float a = 0.f;
#pragma unroll
        for (int i = 0; i < 8; i++) a += rowp[i * 32 + lane] * q[i * 32 + lane];
#pragma unroll
        for (int off = 16; off; off >>= 1) a += __shfl_xor_sync(0xffffffffu, a, off);
        if (lane == 0) sc[m] = a;
    }
    __syncthreads();
    float v = 0.f, e = 0.f;
    if (tid < 512) {
        v = sc[tid];
        float mx = v;
#pragma unroll
        for (int off = 16; off; off >>= 1) mx = fmaxf(mx, __shfl_xor_sync(0xffffffffu, mx, off));
        if (lane == 0) red[w] = mx;
    }
    __syncthreads();
    if (tid == 0) {
        float m8 = red[0];
        for (int i = 1; i < 16; i++) m8 = fmaxf(m8, red[i]);
        red[32] = m8;
    }
    __syncthreads();
    if (tid < 512) {
        e = expf(v - red[32]);
        float s = e;
#pragma unroll
        for (int off = 16; off; off >>= 1) s += __shfl_xor_sync(0xffffffffu, s, off);
        if (lane == 0) red[16 + w] = s;
    }
    __syncthreads();
    if (tid == 0) {
        float t = 0.f;
        for (int i = 0; i < 16; i++) t += red[16 + i];
        red[33] = t;
    }
    __syncthreads();
    if (tid < 512) sc[tid] = e * (1.0f / red[33]);
    __syncthreads();
    int qd = tid >> 8, ee = tid & 255;
    float acc = 0.f;
#pragma unroll 4
    for (int m = qd * 128; m < qd * 128 + 128; m++)
        acc += sc[m] * MA[(size_t)m * NE + ee];
    part[qd][ee] = acc;
    __syncthreads();
    if (tid < NE)
        q[tid] += part[0][tid] + part[1][tid] + part[2][tid] + part[3][tid];
    __syncthreads();
}

__global__ void k_enc() {
    __shared__ float q[NE];
    __shared__ float sc[NM];
    __shared__ float red[40];
    __shared__ float part[4][NE];
    int b = blockIdx.x;
    int tid = threadIdx.x;   // 1024 threads
    const float* T0 = g_mem + ((size_t)0 * NB * NM + (size_t)b * NM) * NE;
    const float* T1 = g_mem + ((size_t)1 * NB * NM + (size_t)b * NM) * NE;
    const float* T2 = g_mem + ((size_t)2 * NB * NM + (size_t)b * NM) * NE;
    {
        int qd = tid >> 8, ee = tid & 255;
        float acc = 0.f;
#pragma unroll 4
        for (int m = qd * 128; m < qd * 128 + 128; m++)
            acc += T0[(size_t)m * NE + ee];
        part[qd][ee] = acc;
        __syncthreads();
        if (tid < NE)
            q[tid] = (part[0][tid] + part[1][tid] + part[2][tid] + part[3][tid])
                     * (1.0f / NM);
        __syncthreads();
    }
    enc_hop(q, sc, red, part, T0, T1);
    enc_hop(q, sc, red, part, T1, T2);
    if (tid < NE) g_q[b * NE + tid] = q[tid];
}

// ---------------- decoder hop 0 + fuse0 (validated R16) ------------------------
__global__ void k_hop_dec(const float* __restrict__ Q) {
    __shared__ float q[8][NE];
    __shared__ float sc[8][NM];
    int b = blockIdx.x, tg = blockIdx.y;
    int tid = threadIdx.x, w = tid >> 5, lane = tid & 31;
#pragma unroll
    for (int i = 0; i < 8; i++)
        q[i][tid] = Q[((size_t)(tg * 8 + i) * NB + b) * NE + tid];
    __syncthreads();
    const float* MS = g_mem + ((size_t)3 * NB * NM + (size_t)b * NM) * NE;
    for (int j = 0; j < 64; j++) {
        int m = w * 64 + j;
        const float* rowp = MS + (size_t)m * NE;
        float mv[8];
#pragma unroll
        for (int i = 0; i < 8; i++) mv[i] = rowp[i * 32 + lane];
#pragma unroll
        for (int t = 0; t < 8; t++) {
            float a = 0.f;
#pragma unroll
            for (int i = 0; i < 8; i++) a += mv[i] * q[t][i * 32 + lane];
#pragma unroll
            for (int off = 16; off; off >>= 1) a += __shfl_xor_sync(0xffffffffu, a, off);
            if (lane == 0) sc[t][m] = a;
        }
    }
    __syncthreads();
    {
        int t = w;
        float mx = -INFINITY;
#pragma unroll
        for (int i = 0; i < 16; i++) mx = fmaxf(mx, sc[t][i * 32 + lane]);
#pragma unroll
        for (int off = 16; off; off >>= 1) mx = fmaxf(mx, __shfl_xor_sync(0xffffffffu, mx, off));
        float ev[16], sum = 0.f;
#pragma unroll
        for (int i = 0; i < 16; i++) { ev[i] = expf(sc[t][i * 32 + lane] - mx); sum += ev[i]; }
#pragma unroll
        for (int off = 16; off; off >>= 1) sum += __shfl_xor_sync(0xffffffffu, sum, off);
        float inv = 1.0f / sum;
#pragma unroll
        for (int i = 0; i < 16; i++) sc[t][i * 32 + lane] = ev[i] * inv;
    }
    __syncthreads();
    const float* MA = g_mem + ((size_t)4 * NB * NM + (size_t)b * NM) * NE;
    float acc[8] = {};
#pragma unroll 4
    for (int m = 0; m < NM; m++) {
        float mval = MA[(size_t)m * NE + tid];
#pragma unroll
        for (int t = 0; t < 8; t++) acc[t] += sc[t][m] * mval;
    }
#pragma unroll
    for (int t = 0; t < 8; t++) {
        size_t row = (size_t)(tg * 8 + t) * NB + b;
        float hq = q[t][tid], o = acc[t];
        g_qc[row * NE + tid] = hq + o;
        g_Xh[row * KX + tid]      = __float2half_rn(hq);
        g_Xh[row * KX + NE + tid] = __float2half_rn(o);
    }
}

// ---------------- register-tiled SGEMM (validated) for gi ----------------
__global__ __launch_bounds__(256, 2)
void k_sgemm(const float* __restrict__ A, const float* __restrict__ B,
             const float* __restrict__ bias, float* __restrict__ C,
             int M, int N, int K) {
    __shared__ float As[8][132];
    __shared__ float Bs[8][132];
    int tid = threadIdx.x;
    int m0 = blockIdx.y * 128, n0 = blockIdx.x * 128;
    int lr = tid >> 1;
    int lk = (tid & 1) * 4;
    const float* Ag = A + (size_t)(m0 + lr) * K + lk;
    const float* Bg = B + (size_t)(n0 + lr) * K + lk;
    int ty = tid >> 4, tx = tid & 15;
    float acc[8][8] = {};
    for (int k0 = 0; k0 < K; k0 += 8) {
        float4 av = *(const float4*)(Ag + k0);
        float4 bv = *(const float4*)(Bg + k0);
        As[lk + 0][lr] = av.x; As[lk + 1][lr] = av.y;
        As[lk + 2][lr] = av.z; As[lk + 3][lr] = av.w;
        Bs[lk + 0][lr] = bv.x; Bs[lk + 1][lr] = bv.y;
        Bs[lk + 2][lr] = bv.z; Bs[lk + 3][lr] = bv.w;
        __syncthreads();
#pragma unroll
        for (int kk = 0; kk < 8; kk++) {
            float a[8], b[8];
            *(float4*)&a[0] = *(const float4*)&As[kk][ty * 4];
            *(float4*)&a[4] = *(const float4*)&As[kk][64 + ty * 4];
            *(float4*)&b[0] = *(const float4*)&Bs[kk][tx * 4];
            *(float4*)&b[4] = *(const float4*)&Bs[kk][64 + tx * 4];
#pragma unroll
            for (int i = 0; i < 8; i++)
#pragma unroll
                for (int j = 0; j < 8; j++) acc[i][j] += a[i] * b[j];
        }
        __syncthreads();
    }
    float bb[8];
#pragma unroll
    for (int j = 0; j < 4; j++) {
        bb[j]     = bias[n0 + tx * 4 + j];
        bb[4 + j] = bias[n0 + 64 + tx * 4 + j];
    }
#pragma unroll
    for (int i = 0; i < 8; i++) {
        int m = m0 + ((i < 4) ? (ty * 4 + i) : (64 + ty * 4 + i - 4));
        float4 c0, c1;
        c0.x = acc[i][0] + bb[0]; c0.y = acc[i][1] + bb[1];
        c0.z = acc[i][2] + bb[2]; c0.w = acc[i][3] + bb[3];
        c1.x = acc[i][4] + bb[4]; c1.y = acc[i][5] + bb[5];
        c1.z = acc[i][6] + bb[6]; c1.w = acc[i][7] + bb[7];
        *(float4*)(C + (size_t)m * N + n0 + tx * 4) = c0;
        *(float4*)(C + (size_t)m * N + n0 + 64 + tx * 4) = c1;
    }
}

// ---------------- GRU v6: 4-k packed W + gi prefetch ---------------------------
__global__ void k_gru(const float* __restrict__ bhh, float* __restrict__ out_h) {
    __shared__ __align__(16) float h[NE];
    __shared__ float gh[NG];
    int b = blockIdx.x, tid = threadIdx.x;   // 768 threads, one gate row each
    if (tid < NE) h[tid] = g_q[b * NE + tid];
    float bias = bhh[tid];
    __syncthreads();
    const uint2* wp = g_Wt4 + tid;
    for (int t = 0; t < NT; t++) {
        // prefetch gate inputs early so their latency hides under the W loop
        float gi0 = 0.f, gi1 = 0.f, gi2 = 0.f;
        if (tid < NE) {
            const float* gi = g_gi + ((size_t)t * NB + b) * NG;
            gi0 = gi[tid]; gi1 = gi[NE + tid]; gi2 = gi[2 * NE + tid];
        }
        float acc = bias;
#pragma unroll 16
        for (int k4 = 0; k4 < NE / 4; k4++) {
            uint2 wv = wp[(size_t)k4 * NG];
            float2 w01 = __half22float2(*(__half2*)&wv.x);
            float2 w23 = __half22float2(*(__half2*)&wv.y);
            float4 hh = *(const float4*)&h[k4 * 4];
            acc += w01.x * hh.x + w01.y * hh.y + w23.x * hh.z + w23.y * hh.w;
        }
        gh[tid] = acc;
        __syncthreads();
        if (tid < NE) {
            float r = 1.0f / (1.0f + expf(-(gi0 + gh[tid])));
            float z = 1.0f / (1.0f + expf(-(gi1 + gh[NE + tid])));
            float n = tanhf(gi2 + r * gh[2 * NE + tid]);
            float hn = (1.0f - z) * n + z * h[tid];
            h[tid] = hn;
            g_H[((size_t)t * NB + b) * NE + tid] = hn;
            if (t == NT - 1) out_h[b * NE + tid] = hn;
        }
        __syncthreads();
    }
}

// ================ combined vocab GEMM + hop1/hop2 front blocks =================
#define MMAH16816(d, a, b) \
  asm volatile("mma.sync.aligned.m16n8k16.row.col.f32.f16.f16.f32 " \
    "{%0,%1,%2,%3}, {%4,%5,%6,%7}, {%8,%9}, {%0,%1,%2,%3};" \
    : "+f"(d[0]), "+f"(d[1]), "+f"(d[2]), "+f"(d[3]) \
    : "r"(a[0]), "r"(a[1]), "r"(a[2]), "r"(a[3]), "r"(b[0]), "r"(b[1]))

__device__ __forceinline__ void cp16(uint32_t dst, const void* src) {
    asm volatile("cp.async.cg.shared.global [%0], [%1], 16;\n" :: "r"(dst), "l"(src));
}

// hop1 + qc update + hop2 raw scores (validated R13-R16)
__device__ void hop12_body(void* smraw, int bx, float* __restrict__ Sout) {
    float (*q)[NE]  = (float(*)[NE])smraw;
    float (*sc)[NM] = (float(*)[NM])((char*)smraw + 8 * NE * sizeof(float));
    int b = bx & (NB - 1), tg = bx >> 6;
    int tid = threadIdx.x, w = tid >> 5, lane = tid & 31;
#pragma unroll
    for (int i = 0; i < 8; i++)
        q[i][tid] = g_qc[((size_t)(tg * 8 + i) * NB + b) * NE + tid];
    __syncthreads();
    const float* MS = g_mem + ((size_t)4 * NB * NM + (size_t)b * NM) * NE;
    const float* MA = g_mem + ((size_t)5 * NB * NM + (size_t)b * NM) * NE;
    for (int j = 0; j < 64; j++) {
        int m = w * 64 + j;
        const float* rowp = MS + (size_t)m * NE;
        float mv[8];
#pragma unroll
        for (int i = 0; i < 8; i++) mv[i] = rowp[i * 32 + lane];
#pragma unroll
        for (int t = 0; t < 8; t++) {
            float a = 0.f;
#pragma unroll
            for (int i = 0; i < 8; i++) a += mv[i] * q[t][i * 32 + lane];
#pragma unroll
            for (int off = 16; off; off >>= 1) a += __shfl_xor_sync(0xffffffffu, a, off);
            if (lane == 0) sc[t][m] = a;
        }
    }
    __syncthreads();
    {
        int t = w;
        float mx = -INFINITY;
#pragma unroll
        for (int i = 0; i < 16; i++) mx = fmaxf(mx, sc[t][i * 32 + lane]);
#pragma unroll
        for (int off = 16; off; off >>= 1) mx = fmaxf(mx, __shfl_xor_sync(0xffffffffu, mx, off));
        float ev[16], sum = 0.f;
#pragma unroll
        for (int i = 0; i < 16; i++) { ev[i] = expf(sc[t][i * 32 + lane] - mx); sum += ev[i]; }
#pragma unroll
        for (int off = 16; off; off >>= 1) sum += __shfl_xor_sync(0xffffffffu, sum, off);
        float inv = 1.0f / sum;
#pragma unroll
        for (int i = 0; i < 16; i++) sc[t][i * 32 + lane] = ev[i] * inv;
    }
    __syncthreads();
    float acc[8] = {};
#pragma unroll 4
    for (int m = 0; m < NM; m++) {
        float mval = MA[(size_t)m * NE + tid];
#pragma unroll
        for (int t = 0; t < 8; t++) acc[t] += sc[t][m] * mval;
    }
    __syncthreads();
#pragma unroll
    for (int t = 0; t < 8; t++) q[t][tid] += acc[t];
    __syncthreads();
    for (int j = 0; j < 64; j++) {
        int m = w * 64 + j;
        const float* rowp = MA + (size_t)m * NE;
        float mv[8];
#pragma unroll
        for (int i = 0; i < 8; i++) mv[i] = rowp[i * 32 + lane];
#pragma unroll
        for (int t = 0; t < 8; t++) {
            float a = 0.f;
#pragma unroll
            for (int i = 0; i < 8; i++) a += mv[i] * q[t][i * 32 + lane];
#pragma unroll
            for (int off = 16; off; off >>= 1) a += __shfl_xor_sync(0xffffffffu, a, off);
            if (lane == 0) sc[t][m] = a;
        }
    }
    __syncthreads();
#pragma unroll
    for (int t = 0; t < 8; t++) {
        size_t row = (size_t)(tg * 8 + t) * NB + b;
        Sout[row * NM + tid]       = sc[t][tid];
        Sout[row * NM + 256 + tid] = sc[t][tid + 256];
    }
}

// grid (256, 17): y==0 -> hop12 (front wave); y>=1 -> GEMM tile.
// GEMM: 4-stage cp.async pipeline, ONE __syncthreads per k-iter.
__global__ __launch_bounds__(256)
void k_hgemm_hop(const float* __restrict__ bias, float* __restrict__ C,
                 float* __restrict__ Sout) {
    __shared__ __align__(16) unsigned char sm[49152];   // 4 stages x 12288
    if (blockIdx.y == 0) { hop12_body(sm, blockIdx.x, Sout); return; }
    if (blockIdx.x >= NV / 128) return;
    int tid = threadIdx.x;
    int n0 = blockIdx.x * 128, m0 = (blockIdx.y - 1) * 128;
    int wid = tid >> 5, lane = tid & 31;
    int wm = (wid >> 2) * 64, wn = (wid & 3) * 32;
    int g = lane >> 2, tg = lane & 3;
    uint32_t sbase = (uint32_t)__cvta_generic_to_shared(sm);
    int lr = tid >> 1, lkc = tid & 1;

    const __half* srcA = g_Xh + (size_t)(m0 + lr) * KX + lkc * 8;
    const __half* srcB = g_Wh + (size_t)(n0 + lr) * KX + lkc * 8;
    uint32_t dbase = sbase + lr * 48 + lkc * 16;

    float acc[4][4][4] = {};

    // prologue: chunks 0, 1 into stages 0, 1
    cp16(dbase,         srcA);
    cp16(dbase + 6144,  srcB);
    asm volatile("cp.async.commit_group;\n" ::);
    cp16(dbase + 12288,        srcA + 16);
    cp16(dbase + 12288 + 6144, srcB + 16);
    asm volatile("cp.async.commit_group;\n" ::);

    for (int it = 0; it < KX / 16; it++) {
        if (it + 2 < KX / 16) {
            uint32_t d2 = dbase + (uint32_t)((it + 2) & 3) * 12288;
            int koff = (it + 2) * 16;
            cp16(d2,        srcA + koff);
            cp16(d2 + 6144, srcB + koff);
            asm volatile("cp.async.commit_group;\n" ::);
            asm volatile("cp.async.wait_group 2;\n" ::);
        } else if (it + 1 < KX / 16) {
            asm volatile("cp.async.wait_group 1;\n" ::);
        } else {
            asm volatile("cp.async.wait_group 0;\n" ::);
        }
        __syncthreads();   // single barrier: chunk `it` visible; stage (it+2)&3 safe to fill next iter
        const char* sb = (const char*)sm + (it & 3) * 12288;
        const __half* Ah = (const __half*)(sb);
        const __half* Bh = (const __half*)(sb + 6144);
        uint32_t ah[4][4];
        int c = tg * 2;
#pragma unroll
        for (int f = 0; f < 4; f++) {
            int r = wm + f * 16 + g;
            ah[f][0] = *(const uint32_t*)&Ah[r * 24 + c];
            ah[f][1] = *(const uint32_t*)&Ah[(r + 8) * 24 + c];
            ah[f][2] = *(const uint32_t*)&Ah[r * 24 + c + 8];
            ah[f][3] = *(const uint32_t*)&Ah[(r + 8) * 24 + c + 8];
        }
#pragma unroll
        for (int fn = 0; fn < 4; fn++) {
            int r = wn + fn * 8 + g;
            uint32_t bh[2];
            bh[0] = *(const uint32_t*)&Bh[r * 24 + c];
            bh[1] = *(const uint32_t*)&Bh[r * 24 + c + 8];
#pragma unroll
            for (int f = 0; f < 4; f++)
                MMAH16816(acc[f][fn], ah[f], bh);
        }
    }
#pragma unroll
    for (int f = 0; f < 4; f++) {
        int rbase = m0 + wm + f * 16 + g;
#pragma unroll
        for (int fn = 0; fn < 4; fn++) {
            int c0 = n0 + wn + fn * 8 + tg * 2;
            float b0v = bias[c0], b1v = bias[c0 + 1];
            float2 v0 = {acc[f][fn][0] + b0v, acc[f][fn][1] + b1v};
            float2 v1 = {acc[f][fn][2] + b0v, acc[f][fn][3] + b1v};
            *(float2*)(C + (size_t)rbase * NV + c0) = v0;
            *(float2*)(C + (size_t)(rbase + 8) * NV + c0) = v1;
        }
    }
}

// ---------------- launch ----------------
extern "C" void kernel_launch(void* const* d_in, const int* in_sizes, int n_in,
                              void* d_out, int out_size) {
    const int*   inp    = (const int*)d_in[0];
    const int*   tgt    = (const int*)d_in[1];
    const float* encC   = (const float*)d_in[2];
    const float* decC   = (const float*)d_in[3];
    const float* W_ih   = (const float*)d_in[4];
    const float* W_hh   = (const float*)d_in[5];
    const float* b_ih   = (const float*)d_in[6];
    const float* b_hh   = (const float*)d_in[7];
    const float* W_voc  = (const float*)d_in[8];
    const float* b_voc  = (const float*)d_in[9];
    float* out = (float*)d_out;

    float *gH, *gxin, *ggi;
    cudaGetSymbolAddress((void**)&gH,   g_H);
    cudaGetSymbolAddress((void**)&gxin, g_xin);
    cudaGetSymbolAddress((void**)&ggi,  g_gi);

    // fused setup: embed + cvt_w + xin (overlapping DRAM streams)
    k_setup<<<NBLK_EMBED + NBLK_CVTW + NBLK_XIN, 256>>>(inp, encC, decC, W_voc, tgt);
    k_whh_t<<<dim3(NG / 32, NE / 32), dim3(32, 32)>>>(W_hh);

    // ---- encoder: mean + 2 hops fused ----
    k_enc<<<NB, 1024>>>();

    // ---- decoder setup + GRU ----
    k_sgemm<<<dim3(NG / 128, (NT * NB) / 128), 256>>>(gxin, W_ih, b_ih, ggi, NT * NB, NG, NE);
    k_gru<<<NB, NG>>>(b_hh, out + OUT_H);

    // ---- decoder hop 0 (fused fuse0) ----
    k_hop_dec<<<dim3(NB, NT / 8), 256>>>(gH);

    // ---- vocab GEMM (4-stage pipeline) + hop1/hop2 front blocks ----
    k_hgemm_hop<<<dim3(256, 17), 256>>>(b_voc, out, out + OUT_PTR);
}